// round 6
// baseline (speedup 1.0000x reference)
#include <cuda_runtime.h>
#include <cuda_bf16.h>
#include <cstdint>

#define S     2048
#define HID   2048
#define NH    32
#define NKV   8
#define HD    64
#define KVDIM (NKV*HD)   // 512
#define CTX   (S-10)     // 2038: rows >= CTX use narrow rope

typedef unsigned long long ull;
typedef __nv_bfloat16 bf16;

__device__ __forceinline__ uint32_t smem_u32(const void* p) {
    uint32_t a;
    asm("{ .reg .u64 t; cvta.to.shared.u64 t, %1; cvt.u32.u64 %0, t; }" : "=r"(a) : "l"(p));
    return a;
}

// ---------------- mma.sync primitives (compute_103-safe) ----------------
__device__ __forceinline__ void cp16(uint32_t s, const void* g) {
    asm volatile("cp.async.cg.shared.global [%0], [%1], 16;" :: "r"(s), "l"(g));
}
#define CP_COMMIT() asm volatile("cp.async.commit_group;" ::: "memory")
#define CP_WAIT1()  asm volatile("cp.async.wait_group 1;" ::: "memory")

__device__ __forceinline__ void ldsm_x4(uint32_t addr, uint32_t& r0, uint32_t& r1,
                                        uint32_t& r2, uint32_t& r3) {
    asm volatile("ldmatrix.sync.aligned.m8n8.x4.shared.b16 {%0,%1,%2,%3}, [%4];"
                 : "=r"(r0), "=r"(r1), "=r"(r2), "=r"(r3) : "r"(addr));
}
__device__ __forceinline__ void ldsm_x4t(uint32_t addr, uint32_t& r0, uint32_t& r1,
                                         uint32_t& r2, uint32_t& r3) {
    asm volatile("ldmatrix.sync.aligned.m8n8.x4.trans.shared.b16 {%0,%1,%2,%3}, [%4];"
                 : "=r"(r0), "=r"(r1), "=r"(r2), "=r"(r3) : "r"(addr));
}
__device__ __forceinline__ void mma16816(float* c, const uint32_t* a, const uint32_t* b) {
    asm volatile(
        "mma.sync.aligned.m16n8k16.row.col.f32.bf16.bf16.f32 "
        "{%0,%1,%2,%3}, {%4,%5,%6,%7}, {%8,%9}, {%0,%1,%2,%3};"
        : "+f"(c[0]), "+f"(c[1]), "+f"(c[2]), "+f"(c[3])
        : "r"(a[0]), "r"(a[1]), "r"(a[2]), "r"(a[3]), "r"(b[0]), "r"(b[1]));
}
__device__ __forceinline__ uint32_t pack_bf16x2(float lo, float hi) {
    uint32_t r; asm("cvt.rn.bf16x2.f32 %0, %1, %2;" : "=r"(r) : "f"(hi), "f"(lo));
    return r;
}

// ---------------- scratch (static device globals; no allocs) ----------------
__device__ float g_Q   [S*HID];
__device__ float g_K   [S*KVDIM];
__device__ float g_V   [S*KVDIM];
__device__ bf16 g_hH[S*HID],     g_hL[S*HID];
__device__ bf16 g_WqH[HID*HID],  g_WqL[HID*HID];
__device__ bf16 g_WkH[KVDIM*HID],g_WkL[KVDIM*HID];
__device__ bf16 g_WvH[KVDIM*HID],g_WvL[KVDIM*HID];
__device__ bf16 g_WoH[HID*HID],  g_WoL[HID*HID];
__device__ bf16 g_aH[S*HID],     g_aL[S*HID];
__device__ bf16 g_Qh[S*HID],    g_Ql[S*HID];
__device__ bf16 g_bKh[S*KVDIM], g_bKl[S*KVDIM];
__device__ bf16 g_nKh[S*KVDIM], g_nKl[S*KVDIM];
__device__ bf16 g_Vh[S*KVDIM],  g_Vl[S*KVDIM];

// ---------------- fp32 -> bf16 hi/lo split ----------------
__global__ __launch_bounds__(256)
void split4_kernel(const float* __restrict__ x, bf16* __restrict__ hi,
                   bf16* __restrict__ lo, int n4)
{
    int i = blockIdx.x * 256 + threadIdx.x;
    if (i >= n4) return;
    float4 v = ((const float4*)x)[i];
    bf16 h0 = __float2bfloat16(v.x);
    bf16 h1 = __float2bfloat16(v.y);
    bf16 h2 = __float2bfloat16(v.z);
    bf16 h3 = __float2bfloat16(v.w);
    __nv_bfloat162 H0 = __nv_bfloat162(h0, h1), H1 = __nv_bfloat162(h2, h3);
    __nv_bfloat162 L0 = __nv_bfloat162(__float2bfloat16(v.x - __bfloat162float(h0)),
                                       __float2bfloat16(v.y - __bfloat162float(h1)));
    __nv_bfloat162 L1 = __nv_bfloat162(__float2bfloat16(v.z - __bfloat162float(h2)),
                                       __float2bfloat16(v.w - __bfloat162float(h3)));
    ((__nv_bfloat162*)hi)[i*2+0] = H0; ((__nv_bfloat162*)hi)[i*2+1] = H1;
    ((__nv_bfloat162*)lo)[i*2+0] = L0; ((__nv_bfloat162*)lo)[i*2+1] = L1;
}

// ---------------- mma.sync split-bf16 GEMM core ------------------------
#define STG      16384
#define SM_STAGE (4*STG)          // 64 KB
#define SM_TOTAL (2*SM_STAGE)     // 128 KB

__device__ __forceinline__ void g_load_stage(
    uint32_t sbuf,
    const bf16* __restrict__ Ah, const bf16* __restrict__ Al,
    const bf16* __restrict__ Bh, const bf16* __restrict__ Bl,
    int mBase, int nBase, int Kdim, int k0, int tid)
{
#pragma unroll
    for (int i = 0; i < 4; i++) {
        int u = i * 256 + tid;
        int r = u >> 3, c = u & 7;
        uint32_t so = (uint32_t)(r * 128 + ((c ^ (r & 7)) << 4));
        size_t eoffA = (size_t)(mBase + r) * Kdim + k0 + c * 8;
        size_t eoffB = (size_t)(nBase + r) * Kdim + k0 + c * 8;
        cp16(sbuf +          so, Ah + eoffA);
        cp16(sbuf +   STG  + so, Al + eoffA);
        cp16(sbuf + 2*STG  + so, Bh + eoffB);
        cp16(sbuf + 3*STG  + so, Bl + eoffB);
    }
}

__device__ __forceinline__ void gemm_body(
    const bf16* __restrict__ Ah, const bf16* __restrict__ Al,
    const bf16* __restrict__ Bh, const bf16* __restrict__ Bl,
    float* __restrict__ C, int Ntot, int Kdim, int mBase, int nBase, uint32_t sb)
{
    const int tid  = threadIdx.x;
    const int lane = tid & 31;
    const int wid  = tid >> 5;
    const int wm   = wid & 1;
    const int wn   = wid >> 1;

    float acc[4][4][4];
#pragma unroll
    for (int i = 0; i < 4; i++)
#pragma unroll
        for (int j = 0; j < 4; j++)
#pragma unroll
            for (int k = 0; k < 4; k++) acc[i][j][k] = 0.0f;

    const int NC = Kdim >> 6;

    g_load_stage(sb,            Ah, Al, Bh, Bl, mBase, nBase, Kdim, 0,  tid);
    CP_COMMIT();
    g_load_stage(sb + SM_STAGE, Ah, Al, Bh, Bl, mBase, nBase, Kdim, 64, tid);
    CP_COMMIT();

    const int aRow = wm * 64;
    const int bRow = wn * 32;

    for (int c = 0; c < NC; c++) {
        CP_WAIT1();
        __syncthreads();
        const uint32_t sbuf = sb + (c & 1) * SM_STAGE;
        const uint32_t sAh = sbuf, sAl = sbuf + STG, sBh = sbuf + 2*STG, sBl = sbuf + 3*STG;

#pragma unroll
        for (int ks = 0; ks < 4; ks++) {
            uint32_t aH[4][4], aL[4][4], bH[4][2], bL[4][2];
            {
                int rA = aRow + (lane & 15);
                int ccA = ks * 2 + (lane >> 4);
#pragma unroll
                for (int mf = 0; mf < 4; mf++) {
                    int r = rA + mf * 16;
                    uint32_t so = (uint32_t)(r * 128 + ((ccA ^ (r & 7)) << 4));
                    ldsm_x4(sAh + so, aH[mf][0], aH[mf][1], aH[mf][2], aH[mf][3]);
                    ldsm_x4(sAl + so, aL[mf][0], aL[mf][1], aL[mf][2], aL[mf][3]);
                }
            }
            {
                int rB0 = bRow + (lane & 7) + ((lane >> 4) << 3);
                int ccB = ks * 2 + ((lane >> 3) & 1);
#pragma unroll
                for (int nf2 = 0; nf2 < 2; nf2++) {
                    int r = rB0 + nf2 * 16;
                    uint32_t so = (uint32_t)(r * 128 + ((ccB ^ (r & 7)) << 4));
                    ldsm_x4(sBh + so, bH[nf2*2][0], bH[nf2*2][1], bH[nf2*2+1][0], bH[nf2*2+1][1]);
                    ldsm_x4(sBl + so, bL[nf2*2][0], bL[nf2*2][1], bL[nf2*2+1][0], bL[nf2*2+1][1]);
                }
            }
#pragma unroll
            for (int mf = 0; mf < 4; mf++)
#pragma unroll
                for (int nf = 0; nf < 4; nf++) {
                    mma16816(acc[mf][nf], aH[mf], bH[nf]);
                    mma16816(acc[mf][nf], aL[mf], bH[nf]);
                    mma16816(acc[mf][nf], aH[mf], bL[nf]);
                }
        }
        __syncthreads();
        if (c + 2 < NC)
            g_load_stage(sb + (c & 1) * SM_STAGE, Ah, Al, Bh, Bl,
                         mBase, nBase, Kdim, (c + 2) * 64, tid);
        CP_COMMIT();
    }

#pragma unroll
    for (int mf = 0; mf < 4; mf++) {
        int row0 = mBase + wm * 64 + mf * 16 + (lane >> 2);
#pragma unroll
        for (int nf = 0; nf < 4; nf++) {
            int col = nBase + wn * 32 + nf * 8 + (lane & 3) * 2;
            *(float2*)&C[(size_t)row0 * Ntot + col]       = make_float2(acc[mf][nf][0], acc[mf][nf][1]);
            *(float2*)&C[(size_t)(row0 + 8) * Ntot + col] = make_float2(acc[mf][nf][2], acc[mf][nf][3]);
        }
    }
}

// fused QKV projection: bx 0..15 -> Q, 16..19 -> K, 20..23 -> V
__global__ __launch_bounds__(256)
void qkv_gemm(const bf16* __restrict__ Ah, const bf16* __restrict__ Al,
              const bf16* __restrict__ WqH, const bf16* __restrict__ WqL,
              const bf16* __restrict__ WkH, const bf16* __restrict__ WkL,
              const bf16* __restrict__ WvH, const bf16* __restrict__ WvL,
              float* __restrict__ Cq, float* __restrict__ Ck, float* __restrict__ Cv)
{
    extern __shared__ char dyns[];
    uint32_t sb = smem_u32(dyns);
    int bx = blockIdx.x, mBase = blockIdx.y * 128;
    if (bx < 16)      gemm_body(Ah, Al, WqH, WqL, Cq, HID,   HID, mBase, bx*128,      sb);
    else if (bx < 20) gemm_body(Ah, Al, WkH, WkL, Ck, KVDIM, HID, mBase, (bx-16)*128, sb);
    else              gemm_body(Ah, Al, WvH, WvL, Cv, KVDIM, HID, mBase, (bx-20)*128, sb);
}

__global__ __launch_bounds__(256)
void wo_gemm(const bf16* __restrict__ Ah, const bf16* __restrict__ Al,
             const bf16* __restrict__ Bh, const bf16* __restrict__ Bl,
             float* __restrict__ C)
{
    extern __shared__ char dyns[];
    uint32_t sb = smem_u32(dyns);
    gemm_body(Ah, Al, Bh, Bl, C, HID, HID, blockIdx.y*128, blockIdx.x*128, sb);
}

// ---------------- RoPE + split: Q (per-row variant, scaled), bK/nK, V ------
__device__ __forceinline__ void split_w(bf16* hp, bf16* lp, float x) {
    bf16 h = __float2bfloat16(x);
    *hp = h;
    *lp = __float2bfloat16(x - __bfloat162float(h));
}

__global__ void rope_split_kernel(const float* __restrict__ Q, const float* __restrict__ K,
                                  const float* __restrict__ V,
                                  bf16* __restrict__ qh, bf16* __restrict__ ql,
                                  bf16* __restrict__ kbh, bf16* __restrict__ kbl,
                                  bf16* __restrict__ knh, bf16* __restrict__ knl,
                                  bf16* __restrict__ vh, bf16* __restrict__ vl)
{
    const int s = blockIdx.x;
    const int tid = threadIdx.x; // 256
    const bool narrowRow = (s >= CTX);
    const float QS = 1.4426950408889634f * 0.125f;   // log2(e)/sqrt(64)

    __shared__ float cb[32], sb[32], cn[32], sn[32];
    if (tid < 32) {
        double inv = pow(10000.0, -(double)tid / 32.0);
        double ab = (double)s * inv;
        double an = ((double)s * 0.25) * inv;
        cb[tid] = (float)cos(ab); sb[tid] = (float)sin(ab);
        cn[tid] = (float)cos(an); sn[tid] = (float)sin(an);
    }
    __syncthreads();

    for (int p = tid; p < NH * 32; p += 256) {
        int h = p >> 5, d = p & 31;
        size_t base = (size_t)s * HID + h * HD;
        float x1 = Q[base + d];
        float x2 = Q[base + d + 32];
        float c  = narrowRow ? cn[d] : cb[d];
        float si = narrowRow ? sn[d] : sb[d];
        split_w(qh + base + d,      ql + base + d,      (x1 * c - x2 * si) * QS);
        split_w(qh + base + d + 32, ql + base + d + 32, (x2 * c + x1 * si) * QS);
    }
    for (int p = tid; p < NKV * 32; p += 256) {
        int h = p >> 5, d = p & 31;
        size_t base = (size_t)s * KVDIM + h * HD;
        float x1 = K[base + d];
        float x2 = K[base + d + 32];
        split_w(kbh + base + d,      kbl + base + d,      x1 * cb[d] - x2 * sb[d]);
        split_w(kbh + base + d + 32, kbl + base + d + 32, x2 * cb[d] + x1 * sb[d]);
        split_w(knh + base + d,      knl + base + d,      x1 * cn[d] - x2 * sn[d]);
        split_w(knh + base + d + 32, knl + base + d + 32, x2 * cn[d] + x1 * sn[d]);
    }
    for (int e = tid; e < KVDIM; e += 256) {
        size_t base = (size_t)s * KVDIM + e;
        split_w(vh + base, vl + base, V[base]);
    }
}

// ---------------- Tensor-core flash attention -------------------------------
// CTA: 64 q-rows x 1 head. 4 warps x 16 rows. Bc=64 key tiles, double-buffered.
// Boost K only; rows >= CTX are recomputed by fixup_kernel afterwards.

__device__ __forceinline__ void fa_load_stage(
    uint32_t sb, int kt, int kvh, int tid,
    const bf16* __restrict__ Kbh, const bf16* __restrict__ Kbl,
    const bf16* __restrict__ Vh, const bf16* __restrict__ Vl)
{
#pragma unroll
    for (int i = 0; i < 4; i++) {
        int u = i * 128 + tid;      // 0..511
        int r = u >> 3, c = u & 7;
        uint32_t so = (uint32_t)(r * 128 + ((c ^ (r & 7)) << 4));
        size_t go = (size_t)(kt * 64 + r) * KVDIM + kvh * 64 + c * 8;
        cp16(sb +         so, Kbh + go);
        cp16(sb + 8192  + so, Kbl + go);
        cp16(sb + 16384 + so, Vh + go);
        cp16(sb + 24576 + so, Vl + go);
    }
}

__device__ __forceinline__ void fa_compute_S(
    float s[8][4], uint32_t sKh, uint32_t sKl,
    const uint32_t qfh[4][4], const uint32_t qfl[4][4], int lane)
{
#pragma unroll
    for (int kk = 0; kk < 4; kk++) {
        uint32_t kh[8][2], kl[8][2];
        int rB0 = (lane & 7) + ((lane >> 4) << 3);
        int ccB = kk * 2 + ((lane >> 3) & 1);
#pragma unroll
        for (int nb = 0; nb < 4; nb++) {
            int r = nb * 16 + rB0;
            uint32_t so = (uint32_t)(r * 128 + ((ccB ^ (r & 7)) << 4));
            ldsm_x4(sKh + so, kh[nb*2][0], kh[nb*2][1], kh[nb*2+1][0], kh[nb*2+1][1]);
            ldsm_x4(sKl + so, kl[nb*2][0], kl[nb*2][1], kl[nb*2+1][0], kl[nb*2+1][1]);
        }
#pragma unroll
        for (int nf = 0; nf < 8; nf++) {
            mma16816(s[nf], qfh[kk], kh[nf]);
            mma16816(s[nf], qfl[kk], kh[nf]);
            mma16816(s[nf], qfh[kk], kl[nf]);
        }
    }
}

#define FA_STAGE 32768
#define FA_SMEM  (16384 + 2*FA_STAGE)   // 81920

__global__ __launch_bounds__(128, 2)
void flash_mma(const bf16* __restrict__ Qh, const bf16* __restrict__ Ql,
               const bf16* __restrict__ Kbh, const bf16* __restrict__ Kbl,
               const bf16* __restrict__ Vh,  const bf16* __restrict__ Vl,
               bf16* __restrict__ aH, bf16* __restrict__ aL)
{
    extern __shared__ char dyn[];
    const uint32_t sQ = smem_u32(dyn);           // Qh 8K | Ql 8K | stage0 | stage1

    const int tid = threadIdx.x, lane = tid & 31, w = tid >> 5;
    const int qt = (S/64 - 1) - (int)blockIdx.x;   // heavy first
    const int h = blockIdx.y, kvh = h >> 2;

    // ---- Q tile load (hi+lo) ----
    {
        const bf16* gQh = Qh + (size_t)(qt * 64) * HID + h * 64;
        const bf16* gQl = Ql + (size_t)(qt * 64) * HID + h * 64;
#pragma unroll
        for (int i = 0; i < 4; i++) {
            int u = i * 128 + tid;
            int r = u >> 3, c = u & 7;
            uint32_t so = (uint32_t)(r * 128 + ((c ^ (r & 7)) << 4));
            cp16(sQ +        so, gQh + (size_t)r * HID + c * 8);
            cp16(sQ + 8192 + so, gQl + (size_t)r * HID + c * 8);
        }
    }
    fa_load_stage(sQ + 16384, 0, kvh, tid, Kbh, Kbl, Vh, Vl);
    CP_COMMIT();
    if (qt >= 1)
        fa_load_stage(sQ + 16384 + FA_STAGE, 1, kvh, tid, Kbh, Kbl, Vh, Vl);
    CP_COMMIT();

    CP_WAIT1();
    __syncthreads();

    // ---- Q fragments (kept in registers for all tiles) ----
    uint32_t qfh[4][4], qfl[4][4];
    {
        int rA = w * 16 + (lane & 15);
#pragma unroll
        for (int kk = 0; kk < 4; kk++) {
            int cc = kk * 2 + (lane >> 4);
            uint32_t so = (uint32_t)(rA * 128 + ((cc ^ (rA & 7)) << 4));
            ldsm_x4(sQ + so,        qfh[kk][0], qfh[kk][1], qfh[kk][2], qfh[kk][3]);
            ldsm_x4(sQ + 8192 + so, qfl[kk][0], qfl[kk][1], qfl[kk][2], qfl[kk][3]);
        }
    }

    float o[8][4];
#pragma unroll
    for (int nf = 0; nf < 8; nf++)
#pragma unroll
        for (int j = 0; j < 4; j++) o[nf][j] = 0.0f;
    float m0 = -1e30f, m1 = -1e30f, l0 = 0.0f, l1 = 0.0f;

    const int rg0 = qt * 64 + w * 16 + (lane >> 2);
    const int rg1 = rg0 + 8;

    for (int kt = 0; kt <= qt; kt++) {
        if (kt) { CP_WAIT1(); __syncthreads(); }
        const uint32_t sb = sQ + 16384 + (kt & 1) * FA_STAGE;

        // ---- S = Q K^T ----
        float s[8][4];
#pragma unroll
        for (int nf = 0; nf < 8; nf++)
#pragma unroll
            for (int j = 0; j < 4; j++) s[nf][j] = 0.0f;
        fa_compute_S(s, sb, sb + 8192, qfh, qfl, lane);

        // ---- causal mask (diagonal tile only) ----
        if (kt == qt) {
#pragma unroll
            for (int nf = 0; nf < 8; nf++) {
                int c0 = kt * 64 + nf * 8 + (lane & 3) * 2;
                if (c0     > rg0) s[nf][0] = -1e30f;
                if (c0 + 1 > rg0) s[nf][1] = -1e30f;
                if (c0     > rg1) s[nf][2] = -1e30f;
                if (c0 + 1 > rg1) s[nf][3] = -1e30f;
            }
        }

        // ---- online softmax (base-2; scale folded into Q) ----
        float mr0 = -1e30f, mr1 = -1e30f;
#pragma unroll
        for (int nf = 0; nf < 8; nf++) {
            mr0 = fmaxf(mr0, fmaxf(s[nf][0], s[nf][1]));
            mr1 = fmaxf(mr1, fmaxf(s[nf][2], s[nf][3]));
        }
        mr0 = fmaxf(mr0, __shfl_xor_sync(0xffffffffu, mr0, 1));
        mr0 = fmaxf(mr0, __shfl_xor_sync(0xffffffffu, mr0, 2));
        mr1 = fmaxf(mr1, __shfl_xor_sync(0xffffffffu, mr1, 1));
        mr1 = fmaxf(mr1, __shfl_xor_sync(0xffffffffu, mr1, 2));

        float mn0 = fmaxf(m0, mr0), mn1 = fmaxf(m1, mr1);
        float sc0 = exp2f(m0 - mn0), sc1 = exp2f(m1 - mn1);
        m0 = mn0; m1 = mn1;
        l0 *= sc0; l1 *= sc1;
#pragma unroll
        for (int nf = 0; nf < 8; nf++) {
            o[nf][0] *= sc0; o[nf][1] *= sc0;
            o[nf][2] *= sc1; o[nf][3] *= sc1;
        }

        uint32_t pH[4][4], pL[4][4];
        float sum0 = 0.0f, sum1 = 0.0f;
#pragma unroll
        for (int nf = 0; nf < 8; nf++) {
            float p0 = exp2f(s[nf][0] - m0), p1 = exp2f(s[nf][1] - m0);
            float p2 = exp2f(s[nf][2] - m1), p3 = exp2f(s[nf][3] - m1);
            sum0 += p0 + p1; sum1 += p2 + p3;
            float r0 = __bfloat162float(__float2bfloat16(p0));
            float r1 = __bfloat162float(__float2bfloat16(p1));
            float r2 = __bfloat162float(__float2bfloat16(p2));
            float r3 = __bfloat162float(__float2bfloat16(p3));
            int kk = nf >> 1;
            int off = (nf & 1) * 2;
            pH[kk][off + 0] = pack_bf16x2(p0, p1);
            pH[kk][off + 1] = pack_bf16x2(p2, p3);
            pL[kk][off + 0] = pack_bf16x2(p0 - r0, p1 - r1);
            pL[kk][off + 1] = pack_bf16x2(p2 - r2, p3 - r3);
        }
        sum0 += __shfl_xor_sync(0xffffffffu, sum0, 1);
        sum0 += __shfl_xor_sync(0xffffffffu, sum0, 2);
        sum1 += __shfl_xor_sync(0xffffffffu, sum1, 1);
        sum1 += __shfl_xor_sync(0xffffffffu, sum1, 2);
        l0 += sum0; l1 += sum1;

        // ---- O += P V ----
        const uint32_t sVh = sb + 16384, sVl = sb + 24576;
#pragma unroll
        for (int kk = 0; kk < 4; kk++) {
            uint32_t vh[8][2], vl[8][2];
            int key0 = kk * 16 + (lane & 7) + ((lane >> 3) & 1) * 8;
#pragma unroll
            for (int nb = 0; nb < 4; nb++) {
                int chunk = nb * 2 + (lane >> 4);
                uint32_t so = (uint32_t)(key0 * 128 + ((chunk ^ (key0 & 7)) << 4));
                ldsm_x4t(sVh + so, vh[nb*2][0], vh[nb*2][1], vh[nb*2+1][0], vh[nb*2+1][1]);
                ldsm_x4t(sVl + so, vl[nb*2][0], vl[nb*2][1], vl[nb*2+1][0], vl[nb*2+1][1]);
            }
#pragma unroll
            for (int nf = 0; nf < 8; nf++) {
                mma16816(o[nf], pH[kk], vh[nf]);
                mma16816(o[nf], pL[kk], vh[nf]);
                mma16816(o[nf], pH[kk], vl[nf]);
            }
        }

        __syncthreads();
        if (kt + 2 <= qt)
            fa_load_stage(sQ + 16384 + (kt & 1) * FA_STAGE, kt + 2, kvh, tid,
                          Kbh, Kbl, Vh, Vl);
        CP_COMMIT();
    }

    // ---- epilogue: write bf16 hi/lo splits of attn output directly ----
    float inv0 = 1.0f / l0, inv1 = 1.0f / l1;
#pragma unroll
    for (int nf = 0; nf < 8; nf++) {
        int col = h * 64 + nf * 8 + (lane & 3) * 2;
        float x0 = o[nf][0]*inv0, x1 = o[nf][1]*inv0;
        float x2 = o[nf][2]*inv1, x3 = o[nf][3]*inv1;
        float r0 = __bfloat162float(__float2bfloat16(x0));
        float r1 = __bfloat162float(__float2bfloat16(x1));
        float r2 = __bfloat162float(__float2bfloat16(x2));
        float r3 = __bfloat162float(__float2bfloat16(x3));
        *(uint32_t*)&aH[(size_t)rg0 * HID + col] = pack_bf16x2(x0, x1);
        *(uint32_t*)&aL[(size_t)rg0 * HID + col] = pack_bf16x2(x0 - r0, x1 - r1);
        *(uint32_t*)&aH[(size_t)rg1 * HID + col] = pack_bf16x2(x2, x3);
        *(uint32_t*)&aL[(size_t)rg1 * HID + col] = pack_bf16x2(x2 - r2, x3 - r3);
    }
}

// ---------------- fixup: recompute rows >= CTX with narrow K (fp32) --------
// One warp per (row, head). 320 warps total = 80 CTAs x 128 threads.
__global__ __launch_bounds__(128)
void fixup_kernel(const bf16* __restrict__ Qh, const bf16* __restrict__ Ql,
                  const bf16* __restrict__ nKh, const bf16* __restrict__ nKl,
                  const bf16* __restrict__ Vh,  const bf16* __restrict__ Vl,
                  bf16* __restrict__ aH, bf16* __restrict__ aL)
{
    const int w = threadIdx.x >> 5, lane = threadIdx.x & 31;
    const int pair = blockIdx.x * 4 + w;          // 0..319
    const int ri = pair >> 5;                      // 0..9
    const int h  = pair & 31;
    const int row = CTX + ri;
    const int kvh = h >> 2;

    __shared__ float qs[4][64];
    for (int d = lane; d < 64; d += 32) {
        size_t off = (size_t)row * HID + h * 64 + d;
        qs[w][d] = __bfloat162float(Qh[off]) + __bfloat162float(Ql[off]);  // scaled, base-2
    }
    __syncwarp();

    float m = -1e30f, l = 0.0f;
    float o[64];
#pragma unroll
    for (int d = 0; d < 64; d++) o[d] = 0.0f;

    const int nkeys = row + 1;
    for (int j = lane; j < nkeys; j += 32) {
        const __nv_bfloat162* kh = (const __nv_bfloat162*)(nKh + (size_t)j * KVDIM + kvh * 64);
        const __nv_bfloat162* kl = (const __nv_bfloat162*)(nKl + (size_t)j * KVDIM + kvh * 64);
        float s = 0.0f;
#pragma unroll
        for (int d2 = 0; d2 < 32; d2++) {
            __nv_bfloat162 a = kh[d2], b = kl[d2];
            s += qs[w][d2*2]   * (__bfloat162float(a.x) + __bfloat162float(b.x));
            s += qs[w][d2*2+1] * (__bfloat162float(a.y) + __bfloat162float(b.y));
        }
        if (s > m) {
            float corr = exp2f(m - s);
            m = s;
            l *= corr;
#pragma unroll
            for (int d = 0; d < 64; d++) o[d] *= corr;
        }
        float p = exp2f(s - m);
        l += p;
        const __nv_bfloat162* vh = (const __nv_bfloat162*)(Vh + (size_t)j * KVDIM + kvh * 64);
        const __nv_bfloat162* vl = (const __nv_bfloat162*)(Vl + (size_t)j * KVDIM + kvh * 64);
#pragma unroll
        for (int d2 = 0; d2 < 32; d2++) {
            __nv_bfloat162 a = vh[d2], b = vl[d2];
            o[d2*2]   += p * (__bfloat162float(a.x) + __bfloat162float(b.x));
            o[d2*2+1] += p * (__bfloat162float(a.y) + __bfloat162float(b.y));
        }
    }

    // butterfly merge across lanes
    for (int delta = 16; delta; delta >>= 1) {
        float mo = __shfl_xor_sync(0xffffffffu, m, delta);
        float lo = __shfl_xor_sync(0xffffffffu, l, delta);
        float mn = fmaxf(m, mo);
        float ca = exp2f(m - mn), cb = exp2f(mo - mn);
        l = l * ca + lo * cb;
#pragma unroll
        for (int d = 0; d < 64; d++) {
            float od = __shfl_xor_sync(0xffffffffu, o[d], delta);
            o[d] = o[d] * ca + od * cb;
        }
        m = mn;
    }

    float inv = 1.0f / l;
    if (lane == 0) {
#pragma unroll
        for (int d = 0; d < 64; d++) qs[w][d] = o[d] * inv;
    }
    __syncwarp();
    for (int d = lane; d < 64; d += 32) {
        float x = qs[w][d];
        bf16 hi = __float2bfloat16(x);
        size_t off = (size_t)row * HID + h * 64 + d;
        aH[off] = hi;
        aL[off] = __float2bfloat16(x - __bfloat162float(hi));
    }
}

// ---------------- launch ----------------
extern "C" void kernel_launch(void* const* d_in, const int* in_sizes, int n_in,
                              void* d_out, int out_size)
{
    const float* hidden = (const float*)d_in[0];
    const float* Wq = (const float*)d_in[3];
    const float* Wk = (const float*)d_in[4];
    const float* Wv = (const float*)d_in[5];
    const float* Wo = (const float*)d_in[6];
    float* out = (float*)d_out;

    float *qB, *kB, *vB;
    cudaGetSymbolAddress((void**)&qB,  g_Q);
    cudaGetSymbolAddress((void**)&kB,  g_K);
    cudaGetSymbolAddress((void**)&vB,  g_V);

    bf16 *hH,*hL,*WqH,*WqL,*WkH,*WkL,*WvH,*WvL,*WoH,*WoL,*aH,*aL;
    cudaGetSymbolAddress((void**)&hH,  g_hH);  cudaGetSymbolAddress((void**)&hL,  g_hL);
    cudaGetSymbolAddress((void**)&WqH, g_WqH); cudaGetSymbolAddress((void**)&WqL, g_WqL);
    cudaGetSymbolAddress((void**)&WkH, g_WkH); cudaGetSymbolAddress((void**)&WkL, g_WkL);
    cudaGetSymbolAddress((void**)&WvH, g_WvH); cudaGetSymbolAddress((void**)&WvL, g_WvL);
    cudaGetSymbolAddress((void**)&WoH, g_WoH); cudaGetSymbolAddress((void**)&WoL, g_WoL);
    cudaGetSymbolAddress((void**)&aH,  g_aH);  cudaGetSymbolAddress((void**)&aL,  g_aL);

    bf16 *Qh,*Ql,*bKh,*bKl,*nKh,*nKl,*Vh,*Vl;
    cudaGetSymbolAddress((void**)&Qh,  g_Qh);  cudaGetSymbolAddress((void**)&Ql,  g_Ql);
    cudaGetSymbolAddress((void**)&bKh, g_bKh); cudaGetSymbolAddress((void**)&bKl, g_bKl);
    cudaGetSymbolAddress((void**)&nKh, g_nKh); cudaGetSymbolAddress((void**)&nKl, g_nKl);
    cudaGetSymbolAddress((void**)&Vh,  g_Vh);  cudaGetSymbolAddress((void**)&Vl,  g_Vl);

    cudaFuncSetAttribute(qkv_gemm, cudaFuncAttributeMaxDynamicSharedMemorySize, SM_TOTAL);
    cudaFuncSetAttribute(wo_gemm,  cudaFuncAttributeMaxDynamicSharedMemorySize, SM_TOTAL);
    cudaFuncSetAttribute(flash_mma, cudaFuncAttributeMaxDynamicSharedMemorySize, FA_SMEM);

    split4_kernel<<<(S*HID/4 + 255)/256, 256>>>(hidden, hH, hL, S*HID/4);
    split4_kernel<<<(HID*HID/4 + 255)/256, 256>>>(Wq, WqH, WqL, HID*HID/4);
    split4_kernel<<<(KVDIM*HID/4 + 255)/256, 256>>>(Wk, WkH, WkL, KVDIM*HID/4);
    split4_kernel<<<(KVDIM*HID/4 + 255)/256, 256>>>(Wv, WvH, WvL, KVDIM*HID/4);
    split4_kernel<<<(HID*HID/4 + 255)/256, 256>>>(Wo, WoH, WoL, HID*HID/4);

    qkv_gemm<<<dim3(24, 16), 256, SM_TOTAL>>>(hH, hL, WqH, WqL, WkH, WkL, WvH, WvL,
                                              qB, kB, vB);

    rope_split_kernel<<<S, 256>>>(qB, kB, vB, Qh, Ql, bKh, bKl, nKh, nKl, Vh, Vl);

    // all 32 q-tiles, heavy first (boost K; narrow rows fixed up after)
    flash_mma<<<dim3(S/64, NH), 128, FA_SMEM>>>(Qh, Ql, bKh, bKl, Vh, Vl, aH, aL);
    fixup_kernel<<<80, 128>>>(Qh, Ql, nKh, nKl, Vh, Vl, aH, aL);

    wo_gemm<<<dim3(16, 16), 256, SM_TOTAL>>>(aH, aL, WoH, WoL, out);
}

// round 7
// speedup vs baseline: 1.6403x; 1.6403x over previous
#include <cuda_runtime.h>
#include <cuda_bf16.h>
#include <cstdint>

#define S     2048
#define HID   2048
#define NH    32
#define NKV   8
#define HD    64
#define KVDIM (NKV*HD)   // 512
#define CTX   (S-10)     // 2038: rows >= CTX use narrow rope

typedef unsigned long long ull;
typedef __nv_bfloat16 bf16;

__device__ __forceinline__ uint32_t smem_u32(const void* p) {
    uint32_t a;
    asm("{ .reg .u64 t; cvta.to.shared.u64 t, %1; cvt.u32.u64 %0, t; }" : "=r"(a) : "l"(p));
    return a;
}

// ---------------- mma.sync primitives (compute_103-safe) ----------------
__device__ __forceinline__ void cp16(uint32_t s, const void* g) {
    asm volatile("cp.async.cg.shared.global [%0], [%1], 16;" :: "r"(s), "l"(g));
}
#define CP_COMMIT() asm volatile("cp.async.commit_group;" ::: "memory")
#define CP_WAIT1()  asm volatile("cp.async.wait_group 1;" ::: "memory")

__device__ __forceinline__ void ldsm_x4(uint32_t addr, uint32_t& r0, uint32_t& r1,
                                        uint32_t& r2, uint32_t& r3) {
    asm volatile("ldmatrix.sync.aligned.m8n8.x4.shared.b16 {%0,%1,%2,%3}, [%4];"
                 : "=r"(r0), "=r"(r1), "=r"(r2), "=r"(r3) : "r"(addr));
}
__device__ __forceinline__ void ldsm_x4t(uint32_t addr, uint32_t& r0, uint32_t& r1,
                                         uint32_t& r2, uint32_t& r3) {
    asm volatile("ldmatrix.sync.aligned.m8n8.x4.trans.shared.b16 {%0,%1,%2,%3}, [%4];"
                 : "=r"(r0), "=r"(r1), "=r"(r2), "=r"(r3) : "r"(addr));
}
__device__ __forceinline__ void mma16816(float* c, const uint32_t* a, const uint32_t* b) {
    asm volatile(
        "mma.sync.aligned.m16n8k16.row.col.f32.bf16.bf16.f32 "
        "{%0,%1,%2,%3}, {%4,%5,%6,%7}, {%8,%9}, {%0,%1,%2,%3};"
        : "+f"(c[0]), "+f"(c[1]), "+f"(c[2]), "+f"(c[3])
        : "r"(a[0]), "r"(a[1]), "r"(a[2]), "r"(a[3]), "r"(b[0]), "r"(b[1]));
}
__device__ __forceinline__ uint32_t pack_bf16x2(float lo, float hi) {
    uint32_t r; asm("cvt.rn.bf16x2.f32 %0, %1, %2;" : "=r"(r) : "f"(hi), "f"(lo));
    return r;
}

// ---------------- scratch (static device globals; no allocs) ----------------
__device__ float g_Q   [S*HID];
__device__ float g_K   [S*KVDIM];
__device__ float g_V   [S*KVDIM];
__device__ bf16 g_hH[S*HID],     g_hL[S*HID];
__device__ bf16 g_WqH[HID*HID],  g_WqL[HID*HID];
__device__ bf16 g_WkH[KVDIM*HID],g_WkL[KVDIM*HID];
__device__ bf16 g_WvH[KVDIM*HID],g_WvL[KVDIM*HID];
__device__ bf16 g_WoH[HID*HID],  g_WoL[HID*HID];
__device__ bf16 g_aH[S*HID],     g_aL[S*HID];
__device__ bf16 g_Qh[S*HID],    g_Ql[S*HID];
__device__ bf16 g_bKh[S*KVDIM], g_bKl[S*KVDIM];
__device__ bf16 g_nKh[S*KVDIM], g_nKl[S*KVDIM];
__device__ bf16 g_Vh[S*KVDIM],  g_Vl[S*KVDIM];

// ---------------- fp32 -> bf16 hi/lo split ----------------
__global__ __launch_bounds__(256)
void split4_kernel(const float* __restrict__ x, bf16* __restrict__ hi,
                   bf16* __restrict__ lo, int n4)
{
    int i = blockIdx.x * 256 + threadIdx.x;
    if (i >= n4) return;
    float4 v = ((const float4*)x)[i];
    bf16 h0 = __float2bfloat16(v.x);
    bf16 h1 = __float2bfloat16(v.y);
    bf16 h2 = __float2bfloat16(v.z);
    bf16 h3 = __float2bfloat16(v.w);
    __nv_bfloat162 H0 = __nv_bfloat162(h0, h1), H1 = __nv_bfloat162(h2, h3);
    __nv_bfloat162 L0 = __nv_bfloat162(__float2bfloat16(v.x - __bfloat162float(h0)),
                                       __float2bfloat16(v.y - __bfloat162float(h1)));
    __nv_bfloat162 L1 = __nv_bfloat162(__float2bfloat16(v.z - __bfloat162float(h2)),
                                       __float2bfloat16(v.w - __bfloat162float(h3)));
    ((__nv_bfloat162*)hi)[i*2+0] = H0; ((__nv_bfloat162*)hi)[i*2+1] = H1;
    ((__nv_bfloat162*)lo)[i*2+0] = L0; ((__nv_bfloat162*)lo)[i*2+1] = L1;
}

// ---------------- mma.sync split-bf16 GEMM core ------------------------
#define STG      16384
#define SM_STAGE (4*STG)          // 64 KB
#define SM_TOTAL (2*SM_STAGE)     // 128 KB

__device__ __forceinline__ void g_load_stage(
    uint32_t sbuf,
    const bf16* __restrict__ Ah, const bf16* __restrict__ Al,
    const bf16* __restrict__ Bh, const bf16* __restrict__ Bl,
    int mBase, int nBase, int Kdim, int k0, int tid)
{
#pragma unroll
    for (int i = 0; i < 4; i++) {
        int u = i * 256 + tid;
        int r = u >> 3, c = u & 7;
        uint32_t so = (uint32_t)(r * 128 + ((c ^ (r & 7)) << 4));
        size_t eoffA = (size_t)(mBase + r) * Kdim + k0 + c * 8;
        size_t eoffB = (size_t)(nBase + r) * Kdim + k0 + c * 8;
        cp16(sbuf +          so, Ah + eoffA);
        cp16(sbuf +   STG  + so, Al + eoffA);
        cp16(sbuf + 2*STG  + so, Bh + eoffB);
        cp16(sbuf + 3*STG  + so, Bl + eoffB);
    }
}

__device__ __forceinline__ void gemm_body(
    const bf16* __restrict__ Ah, const bf16* __restrict__ Al,
    const bf16* __restrict__ Bh, const bf16* __restrict__ Bl,
    float* __restrict__ C, int Ntot, int Kdim, int mBase, int nBase, uint32_t sb)
{
    const int tid  = threadIdx.x;
    const int lane = tid & 31;
    const int wid  = tid >> 5;
    const int wm   = wid & 1;
    const int wn   = wid >> 1;

    float acc[4][4][4];
#pragma unroll
    for (int i = 0; i < 4; i++)
#pragma unroll
        for (int j = 0; j < 4; j++)
#pragma unroll
            for (int k = 0; k < 4; k++) acc[i][j][k] = 0.0f;

    const int NC = Kdim >> 6;

    g_load_stage(sb,            Ah, Al, Bh, Bl, mBase, nBase, Kdim, 0,  tid);
    CP_COMMIT();
    g_load_stage(sb + SM_STAGE, Ah, Al, Bh, Bl, mBase, nBase, Kdim, 64, tid);
    CP_COMMIT();

    const int aRow = wm * 64;
    const int bRow = wn * 32;

    for (int c = 0; c < NC; c++) {
        CP_WAIT1();
        __syncthreads();
        const uint32_t sbuf = sb + (c & 1) * SM_STAGE;
        const uint32_t sAh = sbuf, sAl = sbuf + STG, sBh = sbuf + 2*STG, sBl = sbuf + 3*STG;

#pragma unroll
        for (int ks = 0; ks < 4; ks++) {
            uint32_t aH[4][4], aL[4][4], bH[4][2], bL[4][2];
            {
                int rA = aRow + (lane & 15);
                int ccA = ks * 2 + (lane >> 4);
#pragma unroll
                for (int mf = 0; mf < 4; mf++) {
                    int r = rA + mf * 16;
                    uint32_t so = (uint32_t)(r * 128 + ((ccA ^ (r & 7)) << 4));
                    ldsm_x4(sAh + so, aH[mf][0], aH[mf][1], aH[mf][2], aH[mf][3]);
                    ldsm_x4(sAl + so, aL[mf][0], aL[mf][1], aL[mf][2], aL[mf][3]);
                }
            }
            {
                int rB0 = bRow + (lane & 7) + ((lane >> 4) << 3);
                int ccB = ks * 2 + ((lane >> 3) & 1);
#pragma unroll
                for (int nf2 = 0; nf2 < 2; nf2++) {
                    int r = rB0 + nf2 * 16;
                    uint32_t so = (uint32_t)(r * 128 + ((ccB ^ (r & 7)) << 4));
                    ldsm_x4(sBh + so, bH[nf2*2][0], bH[nf2*2][1], bH[nf2*2+1][0], bH[nf2*2+1][1]);
                    ldsm_x4(sBl + so, bL[nf2*2][0], bL[nf2*2][1], bL[nf2*2+1][0], bL[nf2*2+1][1]);
                }
            }
#pragma unroll
            for (int mf = 0; mf < 4; mf++)
#pragma unroll
                for (int nf = 0; nf < 4; nf++) {
                    mma16816(acc[mf][nf], aH[mf], bH[nf]);
                    mma16816(acc[mf][nf], aL[mf], bH[nf]);
                    mma16816(acc[mf][nf], aH[mf], bL[nf]);
                }
        }
        __syncthreads();
        if (c + 2 < NC)
            g_load_stage(sb + (c & 1) * SM_STAGE, Ah, Al, Bh, Bl,
                         mBase, nBase, Kdim, (c + 2) * 64, tid);
        CP_COMMIT();
    }

#pragma unroll
    for (int mf = 0; mf < 4; mf++) {
        int row0 = mBase + wm * 64 + mf * 16 + (lane >> 2);
#pragma unroll
        for (int nf = 0; nf < 4; nf++) {
            int col = nBase + wn * 32 + nf * 8 + (lane & 3) * 2;
            *(float2*)&C[(size_t)row0 * Ntot + col]       = make_float2(acc[mf][nf][0], acc[mf][nf][1]);
            *(float2*)&C[(size_t)(row0 + 8) * Ntot + col] = make_float2(acc[mf][nf][2], acc[mf][nf][3]);
        }
    }
}

// fused QKV projection: bx 0..15 -> Q, 16..19 -> K, 20..23 -> V
__global__ __launch_bounds__(256)
void qkv_gemm(const bf16* __restrict__ Ah, const bf16* __restrict__ Al,
              const bf16* __restrict__ WqH, const bf16* __restrict__ WqL,
              const bf16* __restrict__ WkH, const bf16* __restrict__ WkL,
              const bf16* __restrict__ WvH, const bf16* __restrict__ WvL,
              float* __restrict__ Cq, float* __restrict__ Ck, float* __restrict__ Cv)
{
    extern __shared__ char dyns[];
    uint32_t sb = smem_u32(dyns);
    int bx = blockIdx.x, mBase = blockIdx.y * 128;
    if (bx < 16)      gemm_body(Ah, Al, WqH, WqL, Cq, HID,   HID, mBase, bx*128,      sb);
    else if (bx < 20) gemm_body(Ah, Al, WkH, WkL, Ck, KVDIM, HID, mBase, (bx-16)*128, sb);
    else              gemm_body(Ah, Al, WvH, WvL, Cv, KVDIM, HID, mBase, (bx-20)*128, sb);
}

__global__ __launch_bounds__(256)
void wo_gemm(const bf16* __restrict__ Ah, const bf16* __restrict__ Al,
             const bf16* __restrict__ Bh, const bf16* __restrict__ Bl,
             float* __restrict__ C)
{
    extern __shared__ char dyns[];
    uint32_t sb = smem_u32(dyns);
    gemm_body(Ah, Al, Bh, Bl, C, HID, HID, blockIdx.y*128, blockIdx.x*128, sb);
}

// ---------------- RoPE + split: Q (per-row variant, scaled), bK/nK, V ------
__device__ __forceinline__ void split_w(bf16* hp, bf16* lp, float x) {
    bf16 h = __float2bfloat16(x);
    *hp = h;
    *lp = __float2bfloat16(x - __bfloat162float(h));
}

__global__ void rope_split_kernel(const float* __restrict__ Q, const float* __restrict__ K,
                                  const float* __restrict__ V,
                                  bf16* __restrict__ qh, bf16* __restrict__ ql,
                                  bf16* __restrict__ kbh, bf16* __restrict__ kbl,
                                  bf16* __restrict__ knh, bf16* __restrict__ knl,
                                  bf16* __restrict__ vh, bf16* __restrict__ vl)
{
    const int s = blockIdx.x;
    const int tid = threadIdx.x; // 256
    const bool narrowRow = (s >= CTX);
    const float QS = 1.4426950408889634f * 0.125f;   // log2(e)/sqrt(64)

    __shared__ float cb[32], sb[32], cn[32], sn[32];
    if (tid < 32) {
        double inv = pow(10000.0, -(double)tid / 32.0);
        double ab = (double)s * inv;
        double an = ((double)s * 0.25) * inv;
        cb[tid] = (float)cos(ab); sb[tid] = (float)sin(ab);
        cn[tid] = (float)cos(an); sn[tid] = (float)sin(an);
    }
    __syncthreads();

    for (int p = tid; p < NH * 32; p += 256) {
        int h = p >> 5, d = p & 31;
        size_t base = (size_t)s * HID + h * HD;
        float x1 = Q[base + d];
        float x2 = Q[base + d + 32];
        float c  = narrowRow ? cn[d] : cb[d];
        float si = narrowRow ? sn[d] : sb[d];
        split_w(qh + base + d,      ql + base + d,      (x1 * c - x2 * si) * QS);
        split_w(qh + base + d + 32, ql + base + d + 32, (x2 * c + x1 * si) * QS);
    }
    for (int p = tid; p < NKV * 32; p += 256) {
        int h = p >> 5, d = p & 31;
        size_t base = (size_t)s * KVDIM + h * HD;
        float x1 = K[base + d];
        float x2 = K[base + d + 32];
        split_w(kbh + base + d,      kbl + base + d,      x1 * cb[d] - x2 * sb[d]);
        split_w(kbh + base + d + 32, kbl + base + d + 32, x2 * cb[d] + x1 * sb[d]);
        split_w(knh + base + d,      knl + base + d,      x1 * cn[d] - x2 * sn[d]);
        split_w(knh + base + d + 32, knl + base + d + 32, x2 * cn[d] + x1 * sn[d]);
    }
    for (int e = tid; e < KVDIM; e += 256) {
        size_t base = (size_t)s * KVDIM + e;
        split_w(vh + base, vl + base, V[base]);
    }
}

// ---------------- Tensor-core flash attention -------------------------------
// CTA: 64 q-rows x 1 head. 4 warps x 16 rows. Bc=64 key tiles, double-buffered.
// Boost K only; rows >= CTX are recomputed by fixup_kernel afterwards.

__device__ __forceinline__ void fa_load_stage(
    uint32_t sb, int kt, int kvh, int tid,
    const bf16* __restrict__ Kbh, const bf16* __restrict__ Kbl,
    const bf16* __restrict__ Vh, const bf16* __restrict__ Vl)
{
#pragma unroll
    for (int i = 0; i < 4; i++) {
        int u = i * 128 + tid;      // 0..511
        int r = u >> 3, c = u & 7;
        uint32_t so = (uint32_t)(r * 128 + ((c ^ (r & 7)) << 4));
        size_t go = (size_t)(kt * 64 + r) * KVDIM + kvh * 64 + c * 8;
        cp16(sb +         so, Kbh + go);
        cp16(sb + 8192  + so, Kbl + go);
        cp16(sb + 16384 + so, Vh + go);
        cp16(sb + 24576 + so, Vl + go);
    }
}

__device__ __forceinline__ void fa_compute_S(
    float s[8][4], uint32_t sKh, uint32_t sKl,
    const uint32_t qfh[4][4], const uint32_t qfl[4][4], int lane)
{
#pragma unroll
    for (int kk = 0; kk < 4; kk++) {
        uint32_t kh[8][2], kl[8][2];
        int rB0 = (lane & 7) + ((lane >> 4) << 3);
        int ccB = kk * 2 + ((lane >> 3) & 1);
#pragma unroll
        for (int nb = 0; nb < 4; nb++) {
            int r = nb * 16 + rB0;
            uint32_t so = (uint32_t)(r * 128 + ((ccB ^ (r & 7)) << 4));
            ldsm_x4(sKh + so, kh[nb*2][0], kh[nb*2][1], kh[nb*2+1][0], kh[nb*2+1][1]);
            ldsm_x4(sKl + so, kl[nb*2][0], kl[nb*2][1], kl[nb*2+1][0], kl[nb*2+1][1]);
        }
#pragma unroll
        for (int nf = 0; nf < 8; nf++) {
            mma16816(s[nf], qfh[kk], kh[nf]);
            mma16816(s[nf], qfl[kk], kh[nf]);
            mma16816(s[nf], qfh[kk], kl[nf]);
        }
    }
}

#define FA_STAGE 32768
#define FA_SMEM  (16384 + 2*FA_STAGE)   // 81920

__global__ __launch_bounds__(128, 2)
void flash_mma(const bf16* __restrict__ Qh, const bf16* __restrict__ Ql,
               const bf16* __restrict__ Kbh, const bf16* __restrict__ Kbl,
               const bf16* __restrict__ Vh,  const bf16* __restrict__ Vl,
               bf16* __restrict__ aH, bf16* __restrict__ aL)
{
    extern __shared__ char dyn[];
    const uint32_t sQ = smem_u32(dyn);           // Qh 8K | Ql 8K | stage0 | stage1

    const int tid = threadIdx.x, lane = tid & 31, w = tid >> 5;
    const int qt = (S/64 - 1) - (int)blockIdx.x;   // heavy first
    const int h = blockIdx.y, kvh = h >> 2;

    // ---- Q tile load (hi+lo) ----
    {
        const bf16* gQh = Qh + (size_t)(qt * 64) * HID + h * 64;
        const bf16* gQl = Ql + (size_t)(qt * 64) * HID + h * 64;
#pragma unroll
        for (int i = 0; i < 4; i++) {
            int u = i * 128 + tid;
            int r = u >> 3, c = u & 7;
            uint32_t so = (uint32_t)(r * 128 + ((c ^ (r & 7)) << 4));
            cp16(sQ +        so, gQh + (size_t)r * HID + c * 8);
            cp16(sQ + 8192 + so, gQl + (size_t)r * HID + c * 8);
        }
    }
    fa_load_stage(sQ + 16384, 0, kvh, tid, Kbh, Kbl, Vh, Vl);
    CP_COMMIT();
    if (qt >= 1)
        fa_load_stage(sQ + 16384 + FA_STAGE, 1, kvh, tid, Kbh, Kbl, Vh, Vl);
    CP_COMMIT();

    CP_WAIT1();
    __syncthreads();

    // ---- Q fragments (kept in registers for all tiles) ----
    uint32_t qfh[4][4], qfl[4][4];
    {
        int rA = w * 16 + (lane & 15);
#pragma unroll
        for (int kk = 0; kk < 4; kk++) {
            int cc = kk * 2 + (lane >> 4);
            uint32_t so = (uint32_t)(rA * 128 + ((cc ^ (rA & 7)) << 4));
            ldsm_x4(sQ + so,        qfh[kk][0], qfh[kk][1], qfh[kk][2], qfh[kk][3]);
            ldsm_x4(sQ + 8192 + so, qfl[kk][0], qfl[kk][1], qfl[kk][2], qfl[kk][3]);
        }
    }

    float o[8][4];
#pragma unroll
    for (int nf = 0; nf < 8; nf++)
#pragma unroll
        for (int j = 0; j < 4; j++) o[nf][j] = 0.0f;
    float m0 = -1e30f, m1 = -1e30f, l0 = 0.0f, l1 = 0.0f;

    const int rg0 = qt * 64 + w * 16 + (lane >> 2);
    const int rg1 = rg0 + 8;

    for (int kt = 0; kt <= qt; kt++) {
        if (kt) { CP_WAIT1(); __syncthreads(); }
        const uint32_t sb = sQ + 16384 + (kt & 1) * FA_STAGE;

        // ---- S = Q K^T ----
        float s[8][4];
#pragma unroll
        for (int nf = 0; nf < 8; nf++)
#pragma unroll
            for (int j = 0; j < 4; j++) s[nf][j] = 0.0f;
        fa_compute_S(s, sb, sb + 8192, qfh, qfl, lane);

        // ---- causal mask (diagonal tile only) ----
        if (kt == qt) {
#pragma unroll
            for (int nf = 0; nf < 8; nf++) {
                int c0 = kt * 64 + nf * 8 + (lane & 3) * 2;
                if (c0     > rg0) s[nf][0] = -1e30f;
                if (c0 + 1 > rg0) s[nf][1] = -1e30f;
                if (c0     > rg1) s[nf][2] = -1e30f;
                if (c0 + 1 > rg1) s[nf][3] = -1e30f;
            }
        }

        // ---- online softmax (base-2; scale folded into Q) ----
        float mr0 = -1e30f, mr1 = -1e30f;
#pragma unroll
        for (int nf = 0; nf < 8; nf++) {
            mr0 = fmaxf(mr0, fmaxf(s[nf][0], s[nf][1]));
            mr1 = fmaxf(mr1, fmaxf(s[nf][2], s[nf][3]));
        }
        mr0 = fmaxf(mr0, __shfl_xor_sync(0xffffffffu, mr0, 1));
        mr0 = fmaxf(mr0, __shfl_xor_sync(0xffffffffu, mr0, 2));
        mr1 = fmaxf(mr1, __shfl_xor_sync(0xffffffffu, mr1, 1));
        mr1 = fmaxf(mr1, __shfl_xor_sync(0xffffffffu, mr1, 2));

        float mn0 = fmaxf(m0, mr0), mn1 = fmaxf(m1, mr1);
        float sc0 = exp2f(m0 - mn0), sc1 = exp2f(m1 - mn1);
        m0 = mn0; m1 = mn1;
        l0 *= sc0; l1 *= sc1;
#pragma unroll
        for (int nf = 0; nf < 8; nf++) {
            o[nf][0] *= sc0; o[nf][1] *= sc0;
            o[nf][2] *= sc1; o[nf][3] *= sc1;
        }

        uint32_t pH[4][4], pL[4][4];
        float sum0 = 0.0f, sum1 = 0.0f;
#pragma unroll
        for (int nf = 0; nf < 8; nf++) {
            float p0 = exp2f(s[nf][0] - m0), p1 = exp2f(s[nf][1] - m0);
            float p2 = exp2f(s[nf][2] - m1), p3 = exp2f(s[nf][3] - m1);
            sum0 += p0 + p1; sum1 += p2 + p3;
            float r0 = __bfloat162float(__float2bfloat16(p0));
            float r1 = __bfloat162float(__float2bfloat16(p1));
            float r2 = __bfloat162float(__float2bfloat16(p2));
            float r3 = __bfloat162float(__float2bfloat16(p3));
            int kk = nf >> 1;
            int off = (nf & 1) * 2;
            pH[kk][off + 0] = pack_bf16x2(p0, p1);
            pH[kk][off + 1] = pack_bf16x2(p2, p3);
            pL[kk][off + 0] = pack_bf16x2(p0 - r0, p1 - r1);
            pL[kk][off + 1] = pack_bf16x2(p2 - r2, p3 - r3);
        }
        sum0 += __shfl_xor_sync(0xffffffffu, sum0, 1);
        sum0 += __shfl_xor_sync(0xffffffffu, sum0, 2);
        sum1 += __shfl_xor_sync(0xffffffffu, sum1, 1);
        sum1 += __shfl_xor_sync(0xffffffffu, sum1, 2);
        l0 += sum0; l1 += sum1;

        // ---- O += P V ----
        const uint32_t sVh = sb + 16384, sVl = sb + 24576;
#pragma unroll
        for (int kk = 0; kk < 4; kk++) {
            uint32_t vh[8][2], vl[8][2];
            int key0 = kk * 16 + (lane & 7) + ((lane >> 3) & 1) * 8;
#pragma unroll
            for (int nb = 0; nb < 4; nb++) {
                int chunk = nb * 2 + (lane >> 4);
                uint32_t so = (uint32_t)(key0 * 128 + ((chunk ^ (key0 & 7)) << 4));
                ldsm_x4t(sVh + so, vh[nb*2][0], vh[nb*2][1], vh[nb*2+1][0], vh[nb*2+1][1]);
                ldsm_x4t(sVl + so, vl[nb*2][0], vl[nb*2][1], vl[nb*2+1][0], vl[nb*2+1][1]);
            }
#pragma unroll
            for (int nf = 0; nf < 8; nf++) {
                mma16816(o[nf], pH[kk], vh[nf]);
                mma16816(o[nf], pL[kk], vh[nf]);
                mma16816(o[nf], pH[kk], vl[nf]);
            }
        }

        __syncthreads();
        if (kt + 2 <= qt)
            fa_load_stage(sQ + 16384 + (kt & 1) * FA_STAGE, kt + 2, kvh, tid,
                          Kbh, Kbl, Vh, Vl);
        CP_COMMIT();
    }

    // ---- epilogue: write bf16 hi/lo splits of attn output directly ----
    float inv0 = 1.0f / l0, inv1 = 1.0f / l1;
#pragma unroll
    for (int nf = 0; nf < 8; nf++) {
        int col = h * 64 + nf * 8 + (lane & 3) * 2;
        float x0 = o[nf][0]*inv0, x1 = o[nf][1]*inv0;
        float x2 = o[nf][2]*inv1, x3 = o[nf][3]*inv1;
        float r0 = __bfloat162float(__float2bfloat16(x0));
        float r1 = __bfloat162float(__float2bfloat16(x1));
        float r2 = __bfloat162float(__float2bfloat16(x2));
        float r3 = __bfloat162float(__float2bfloat16(x3));
        *(uint32_t*)&aH[(size_t)rg0 * HID + col] = pack_bf16x2(x0, x1);
        *(uint32_t*)&aL[(size_t)rg0 * HID + col] = pack_bf16x2(x0 - r0, x1 - r1);
        *(uint32_t*)&aH[(size_t)rg1 * HID + col] = pack_bf16x2(x2, x3);
        *(uint32_t*)&aL[(size_t)rg1 * HID + col] = pack_bf16x2(x2 - r2, x3 - r3);
    }
}

// ---------------- fixup: recompute rows >= CTX with narrow K (coalesced) ----
// One CTA per (row, head): 320 CTAs x 256 threads. Phase 1: warp per key,
// lanes across dims (coalesced K loads). Phase 2: thread = (dim, key-chunk),
// coalesced V loads. Scores staged in smem; exact softmax (no online pass).
__global__ __launch_bounds__(256)
void fixup_kernel(const bf16* __restrict__ Qh, const bf16* __restrict__ Ql,
                  const bf16* __restrict__ nKh, const bf16* __restrict__ nKl,
                  const bf16* __restrict__ Vh,  const bf16* __restrict__ Vl,
                  bf16* __restrict__ aH, bf16* __restrict__ aL)
{
    const int pair = blockIdx.x;            // 0..319
    const int ri = pair >> 5;                // 0..9
    const int h  = pair & 31;
    const int row = CTX + ri;
    const int kvh = h >> 2;
    const int tid = threadIdx.x, lane = tid & 31, w = tid >> 5;
    const int nkeys = row + 1;

    __shared__ float qsm[64];
    __shared__ float sc[S];
    __shared__ float red[8];
    __shared__ float oacc[4][64];

    if (tid < 64) {
        size_t off = (size_t)row * HID + h * 64 + tid;
        qsm[tid] = __bfloat162float(Qh[off]) + __bfloat162float(Ql[off]);  // scaled (base-2)
    }
    __syncthreads();

    // ---- phase 1: scores (warp per key, lanes over dims) ----
    const float q0 = qsm[lane * 2], q1 = qsm[lane * 2 + 1];
    for (int j = w; j < nkeys; j += 8) {
        size_t off = (size_t)j * KVDIM + kvh * 64;
        __nv_bfloat162 a = ((const __nv_bfloat162*)(nKh + off))[lane];
        __nv_bfloat162 b = ((const __nv_bfloat162*)(nKl + off))[lane];
        float kx = __bfloat162float(a.x) + __bfloat162float(b.x);
        float ky = __bfloat162float(a.y) + __bfloat162float(b.y);
        float s = q0 * kx + q1 * ky;
#pragma unroll
        for (int d = 16; d; d >>= 1) s += __shfl_xor_sync(0xffffffffu, s, d);
        if (lane == 0) sc[j] = s;
    }
    __syncthreads();

    // ---- max reduce ----
    float mym = -1e30f;
    for (int j = tid; j < nkeys; j += 256) mym = fmaxf(mym, sc[j]);
#pragma unroll
    for (int d = 16; d; d >>= 1) mym = fmaxf(mym, __shfl_xor_sync(0xffffffffu, mym, d));
    if (lane == 0) red[w] = mym;
    __syncthreads();
    float M = red[0];
#pragma unroll
    for (int i = 1; i < 8; i++) M = fmaxf(M, red[i]);
    __syncthreads();

    // ---- p = exp2(s - M), sum ----
    float ls = 0.0f;
    for (int j = tid; j < nkeys; j += 256) {
        float p = exp2f(sc[j] - M);
        sc[j] = p;
        ls += p;
    }
#pragma unroll
    for (int d = 16; d; d >>= 1) ls += __shfl_xor_sync(0xffffffffu, ls, d);
    if (lane == 0) red[w] = ls;
    __syncthreads();
    float L = red[0];
#pragma unroll
    for (int i = 1; i < 8; i++) L += red[i];

    // ---- phase 2: O = sum p_j V_j (thread = dim x key-chunk, coalesced) ----
    const int d = tid & 63, ch = tid >> 6;   // 4 chunks
    float acc = 0.0f;
    for (int j = ch; j < nkeys; j += 4) {
        size_t off = (size_t)j * KVDIM + kvh * 64 + d;
        acc += sc[j] * (__bfloat162float(Vh[off]) + __bfloat162float(Vl[off]));
    }
    oacc[ch][d] = acc;
    __syncthreads();

    if (tid < 64) {
        float o = (oacc[0][tid] + oacc[1][tid] + oacc[2][tid] + oacc[3][tid]) / L;
        size_t off = (size_t)row * HID + h * 64 + tid;
        bf16 hi = __float2bfloat16(o);
        aH[off] = hi;
        aL[off] = __float2bfloat16(o - __bfloat162float(hi));
    }
}

// ---------------- launch ----------------
extern "C" void kernel_launch(void* const* d_in, const int* in_sizes, int n_in,
                              void* d_out, int out_size)
{
    const float* hidden = (const float*)d_in[0];
    const float* Wq = (const float*)d_in[3];
    const float* Wk = (const float*)d_in[4];
    const float* Wv = (const float*)d_in[5];
    const float* Wo = (const float*)d_in[6];
    float* out = (float*)d_out;

    float *qB, *kB, *vB;
    cudaGetSymbolAddress((void**)&qB,  g_Q);
    cudaGetSymbolAddress((void**)&kB,  g_K);
    cudaGetSymbolAddress((void**)&vB,  g_V);

    bf16 *hH,*hL,*WqH,*WqL,*WkH,*WkL,*WvH,*WvL,*WoH,*WoL,*aH,*aL;
    cudaGetSymbolAddress((void**)&hH,  g_hH);  cudaGetSymbolAddress((void**)&hL,  g_hL);
    cudaGetSymbolAddress((void**)&WqH, g_WqH); cudaGetSymbolAddress((void**)&WqL, g_WqL);
    cudaGetSymbolAddress((void**)&WkH, g_WkH); cudaGetSymbolAddress((void**)&WkL, g_WkL);
    cudaGetSymbolAddress((void**)&WvH, g_WvH); cudaGetSymbolAddress((void**)&WvL, g_WvL);
    cudaGetSymbolAddress((void**)&WoH, g_WoH); cudaGetSymbolAddress((void**)&WoL, g_WoL);
    cudaGetSymbolAddress((void**)&aH,  g_aH);  cudaGetSymbolAddress((void**)&aL,  g_aL);

    bf16 *Qh,*Ql,*bKh,*bKl,*nKh,*nKl,*Vh,*Vl;
    cudaGetSymbolAddress((void**)&Qh,  g_Qh);  cudaGetSymbolAddress((void**)&Ql,  g_Ql);
    cudaGetSymbolAddress((void**)&bKh, g_bKh); cudaGetSymbolAddress((void**)&bKl, g_bKl);
    cudaGetSymbolAddress((void**)&nKh, g_nKh); cudaGetSymbolAddress((void**)&nKl, g_nKl);
    cudaGetSymbolAddress((void**)&Vh,  g_Vh);  cudaGetSymbolAddress((void**)&Vl,  g_Vl);

    cudaFuncSetAttribute(qkv_gemm, cudaFuncAttributeMaxDynamicSharedMemorySize, SM_TOTAL);
    cudaFuncSetAttribute(wo_gemm,  cudaFuncAttributeMaxDynamicSharedMemorySize, SM_TOTAL);
    cudaFuncSetAttribute(flash_mma, cudaFuncAttributeMaxDynamicSharedMemorySize, FA_SMEM);

    split4_kernel<<<(S*HID/4 + 255)/256, 256>>>(hidden, hH, hL, S*HID/4);
    split4_kernel<<<(HID*HID/4 + 255)/256, 256>>>(Wq, WqH, WqL, HID*HID/4);
    split4_kernel<<<(KVDIM*HID/4 + 255)/256, 256>>>(Wk, WkH, WkL, KVDIM*HID/4);
    split4_kernel<<<(KVDIM*HID/4 + 255)/256, 256>>>(Wv, WvH, WvL, KVDIM*HID/4);
    split4_kernel<<<(HID*HID/4 + 255)/256, 256>>>(Wo, WoH, WoL, HID*HID/4);

    qkv_gemm<<<dim3(24, 16), 256, SM_TOTAL>>>(hH, hL, WqH, WqL, WkH, WkL, WvH, WvL,
                                              qB, kB, vB);

    rope_split_kernel<<<S, 256>>>(qB, kB, vB, Qh, Ql, bKh, bKl, nKh, nKl, Vh, Vl);

    // all 32 q-tiles, heavy first (boost K; narrow rows fixed up after)
    flash_mma<<<dim3(S/64, NH), 128, FA_SMEM>>>(Qh, Ql, bKh, bKl, Vh, Vl, aH, aL);
    fixup_kernel<<<320, 256>>>(Qh, Ql, nKh, nKl, Vh, Vl, aH, aL);

    wo_gemm<<<dim3(16, 16), 256, SM_TOTAL>>>(aH, aL, WoH, WoL, out);
}

// round 8
// speedup vs baseline: 1.6550x; 1.0090x over previous
#include <cuda_runtime.h>
#include <cuda_bf16.h>
#include <cstdint>

#define S     2048
#define HID   2048
#define NH    32
#define NKV   8
#define HD    64
#define KVDIM (NKV*HD)   // 512
#define CTX   (S-10)     // 2038: rows >= CTX use narrow rope

typedef unsigned long long ull;
typedef __nv_bfloat16 bf16;

__device__ __forceinline__ uint32_t smem_u32(const void* p) {
    uint32_t a;
    asm("{ .reg .u64 t; cvta.to.shared.u64 t, %1; cvt.u32.u64 %0, t; }" : "=r"(a) : "l"(p));
    return a;
}

// ---------------- mma.sync primitives (compute_103-safe) ----------------
__device__ __forceinline__ void cp16(uint32_t s, const void* g) {
    asm volatile("cp.async.cg.shared.global [%0], [%1], 16;" :: "r"(s), "l"(g));
}
#define CP_COMMIT() asm volatile("cp.async.commit_group;" ::: "memory")
#define CP_WAIT1()  asm volatile("cp.async.wait_group 1;" ::: "memory")

__device__ __forceinline__ void ldsm_x4(uint32_t addr, uint32_t& r0, uint32_t& r1,
                                        uint32_t& r2, uint32_t& r3) {
    asm volatile("ldmatrix.sync.aligned.m8n8.x4.shared.b16 {%0,%1,%2,%3}, [%4];"
                 : "=r"(r0), "=r"(r1), "=r"(r2), "=r"(r3) : "r"(addr));
}
__device__ __forceinline__ void ldsm_x4t(uint32_t addr, uint32_t& r0, uint32_t& r1,
                                         uint32_t& r2, uint32_t& r3) {
    asm volatile("ldmatrix.sync.aligned.m8n8.x4.trans.shared.b16 {%0,%1,%2,%3}, [%4];"
                 : "=r"(r0), "=r"(r1), "=r"(r2), "=r"(r3) : "r"(addr));
}
__device__ __forceinline__ void mma16816(float* c, const uint32_t* a, const uint32_t* b) {
    asm volatile(
        "mma.sync.aligned.m16n8k16.row.col.f32.bf16.bf16.f32 "
        "{%0,%1,%2,%3}, {%4,%5,%6,%7}, {%8,%9}, {%0,%1,%2,%3};"
        : "+f"(c[0]), "+f"(c[1]), "+f"(c[2]), "+f"(c[3])
        : "r"(a[0]), "r"(a[1]), "r"(a[2]), "r"(a[3]), "r"(b[0]), "r"(b[1]));
}
__device__ __forceinline__ uint32_t pack_bf16x2(float lo, float hi) {
    uint32_t r; asm("cvt.rn.bf16x2.f32 %0, %1, %2;" : "=r"(r) : "f"(hi), "f"(lo));
    return r;
}

// ---------------- scratch (static device globals; no allocs) ----------------
__device__ float g_Q   [S*HID];
__device__ float g_K   [S*KVDIM];
__device__ float g_V   [S*KVDIM];
__device__ float g_attn[S*HID];
__device__ bf16 g_hH[S*HID],     g_hL[S*HID];
__device__ bf16 g_WqH[HID*HID],  g_WqL[HID*HID];
__device__ bf16 g_WkH[KVDIM*HID],g_WkL[KVDIM*HID];
__device__ bf16 g_WvH[KVDIM*HID],g_WvL[KVDIM*HID];
__device__ bf16 g_WoH[HID*HID],  g_WoL[HID*HID];
__device__ bf16 g_aH[S*HID],     g_aL[S*HID];
__device__ bf16 g_Qh[S*HID],    g_Ql[S*HID];
__device__ bf16 g_bKh[S*KVDIM], g_bKl[S*KVDIM];
__device__ bf16 g_nKh[S*KVDIM], g_nKl[S*KVDIM];
__device__ bf16 g_Vh[S*KVDIM],  g_Vl[S*KVDIM];

// ---------------- fp32 -> bf16 hi/lo split ----------------
__device__ __forceinline__ void split_body(const float* __restrict__ x,
                                           bf16* __restrict__ hi, bf16* __restrict__ lo,
                                           int i)
{
    float4 v = ((const float4*)x)[i];
    bf16 h0 = __float2bfloat16(v.x);
    bf16 h1 = __float2bfloat16(v.y);
    bf16 h2 = __float2bfloat16(v.z);
    bf16 h3 = __float2bfloat16(v.w);
    __nv_bfloat162 H0 = __nv_bfloat162(h0, h1), H1 = __nv_bfloat162(h2, h3);
    __nv_bfloat162 L0 = __nv_bfloat162(__float2bfloat16(v.x - __bfloat162float(h0)),
                                       __float2bfloat16(v.y - __bfloat162float(h1)));
    __nv_bfloat162 L1 = __nv_bfloat162(__float2bfloat16(v.z - __bfloat162float(h2)),
                                       __float2bfloat16(v.w - __bfloat162float(h3)));
    ((__nv_bfloat162*)hi)[i*2+0] = H0; ((__nv_bfloat162*)hi)[i*2+1] = H1;
    ((__nv_bfloat162*)lo)[i*2+0] = L0; ((__nv_bfloat162*)lo)[i*2+1] = L1;
}

__global__ __launch_bounds__(256)
void split4_kernel(const float* __restrict__ x, bf16* __restrict__ hi,
                   bf16* __restrict__ lo, int n4)
{
    int i = blockIdx.x * 256 + threadIdx.x;
    if (i >= n4) return;
    split_body(x, hi, lo, i);
}

// merged split of all 5 inputs in ONE launch.
// regions (in float4 units): hidden 1048576 | Wq 1048576 | Wk 262144 | Wv 262144 | Wo 1048576
__global__ __launch_bounds__(256)
void split_all_kernel(const float* __restrict__ hid, const float* __restrict__ Wq,
                      const float* __restrict__ Wk,  const float* __restrict__ Wv,
                      const float* __restrict__ Wo,
                      bf16* __restrict__ hH, bf16* __restrict__ hL,
                      bf16* __restrict__ qH, bf16* __restrict__ qL,
                      bf16* __restrict__ kH, bf16* __restrict__ kL,
                      bf16* __restrict__ vH, bf16* __restrict__ vL,
                      bf16* __restrict__ oH, bf16* __restrict__ oL)
{
    int g = blockIdx.x * 256 + threadIdx.x;
    const int R0 = 1048576, R1 = R0 + 1048576, R2 = R1 + 262144, R3 = R2 + 262144;
    if (g < R0)            split_body(hid, hH, hL, g);
    else if (g < R1)       split_body(Wq,  qH, qL, g - R0);
    else if (g < R2)       split_body(Wk,  kH, kL, g - R1);
    else if (g < R3)       split_body(Wv,  vH, vL, g - R2);
    else                   split_body(Wo,  oH, oL, g - R3);
}

// ---------------- mma.sync split-bf16 GEMM core ------------------------
#define STG      16384
#define SM_STAGE (4*STG)          // 64 KB
#define SM_TOTAL (2*SM_STAGE)     // 128 KB

__device__ __forceinline__ void g_load_stage(
    uint32_t sbuf,
    const bf16* __restrict__ Ah, const bf16* __restrict__ Al,
    const bf16* __restrict__ Bh, const bf16* __restrict__ Bl,
    int mBase, int nBase, int Kdim, int k0, int tid)
{
#pragma unroll
    for (int i = 0; i < 4; i++) {
        int u = i * 256 + tid;
        int r = u >> 3, c = u & 7;
        uint32_t so = (uint32_t)(r * 128 + ((c ^ (r & 7)) << 4));
        size_t eoffA = (size_t)(mBase + r) * Kdim + k0 + c * 8;
        size_t eoffB = (size_t)(nBase + r) * Kdim + k0 + c * 8;
        cp16(sbuf +          so, Ah + eoffA);
        cp16(sbuf +   STG  + so, Al + eoffA);
        cp16(sbuf + 2*STG  + so, Bh + eoffB);
        cp16(sbuf + 3*STG  + so, Bl + eoffB);
    }
}

__device__ __forceinline__ void gemm_body(
    const bf16* __restrict__ Ah, const bf16* __restrict__ Al,
    const bf16* __restrict__ Bh, const bf16* __restrict__ Bl,
    float* __restrict__ C, int Ntot, int Kdim, int mBase, int nBase, uint32_t sb)
{
    const int tid  = threadIdx.x;
    const int lane = tid & 31;
    const int wid  = tid >> 5;
    const int wm   = wid & 1;
    const int wn   = wid >> 1;

    float acc[4][4][4];
#pragma unroll
    for (int i = 0; i < 4; i++)
#pragma unroll
        for (int j = 0; j < 4; j++)
#pragma unroll
            for (int k = 0; k < 4; k++) acc[i][j][k] = 0.0f;

    const int NC = Kdim >> 6;

    g_load_stage(sb,            Ah, Al, Bh, Bl, mBase, nBase, Kdim, 0,  tid);
    CP_COMMIT();
    g_load_stage(sb + SM_STAGE, Ah, Al, Bh, Bl, mBase, nBase, Kdim, 64, tid);
    CP_COMMIT();

    const int aRow = wm * 64;
    const int bRow = wn * 32;

    for (int c = 0; c < NC; c++) {
        CP_WAIT1();
        __syncthreads();
        const uint32_t sbuf = sb + (c & 1) * SM_STAGE;
        const uint32_t sAh = sbuf, sAl = sbuf + STG, sBh = sbuf + 2*STG, sBl = sbuf + 3*STG;

#pragma unroll
        for (int ks = 0; ks < 4; ks++) {
            uint32_t aH[4][4], aL[4][4], bH[4][2], bL[4][2];
            {
                int rA = aRow + (lane & 15);
                int ccA = ks * 2 + (lane >> 4);
#pragma unroll
                for (int mf = 0; mf < 4; mf++) {
                    int r = rA + mf * 16;
                    uint32_t so = (uint32_t)(r * 128 + ((ccA ^ (r & 7)) << 4));
                    ldsm_x4(sAh + so, aH[mf][0], aH[mf][1], aH[mf][2], aH[mf][3]);
                    ldsm_x4(sAl + so, aL[mf][0], aL[mf][1], aL[mf][2], aL[mf][3]);
                }
            }
            {
                int rB0 = bRow + (lane & 7) + ((lane >> 4) << 3);
                int ccB = ks * 2 + ((lane >> 3) & 1);
#pragma unroll
                for (int nf2 = 0; nf2 < 2; nf2++) {
                    int r = rB0 + nf2 * 16;
                    uint32_t so = (uint32_t)(r * 128 + ((ccB ^ (r & 7)) << 4));
                    ldsm_x4(sBh + so, bH[nf2*2][0], bH[nf2*2][1], bH[nf2*2+1][0], bH[nf2*2+1][1]);
                    ldsm_x4(sBl + so, bL[nf2*2][0], bL[nf2*2][1], bL[nf2*2+1][0], bL[nf2*2+1][1]);
                }
            }
#pragma unroll
            for (int mf = 0; mf < 4; mf++)
#pragma unroll
                for (int nf = 0; nf < 4; nf++) {
                    mma16816(acc[mf][nf], aH[mf], bH[nf]);
                    mma16816(acc[mf][nf], aL[mf], bH[nf]);
                    mma16816(acc[mf][nf], aH[mf], bL[nf]);
                }
        }
        __syncthreads();
        if (c + 2 < NC)
            g_load_stage(sb + (c & 1) * SM_STAGE, Ah, Al, Bh, Bl,
                         mBase, nBase, Kdim, (c + 2) * 64, tid);
        CP_COMMIT();
    }

#pragma unroll
    for (int mf = 0; mf < 4; mf++) {
        int row0 = mBase + wm * 64 + mf * 16 + (lane >> 2);
#pragma unroll
        for (int nf = 0; nf < 4; nf++) {
            int col = nBase + wn * 32 + nf * 8 + (lane & 3) * 2;
            *(float2*)&C[(size_t)row0 * Ntot + col]       = make_float2(acc[mf][nf][0], acc[mf][nf][1]);
            *(float2*)&C[(size_t)(row0 + 8) * Ntot + col] = make_float2(acc[mf][nf][2], acc[mf][nf][3]);
        }
    }
}

// fused QKV projection: bx 0..15 -> Q, 16..19 -> K, 20..23 -> V
__global__ __launch_bounds__(256)
void qkv_gemm(const bf16* __restrict__ Ah, const bf16* __restrict__ Al,
              const bf16* __restrict__ WqH, const bf16* __restrict__ WqL,
              const bf16* __restrict__ WkH, const bf16* __restrict__ WkL,
              const bf16* __restrict__ WvH, const bf16* __restrict__ WvL,
              float* __restrict__ Cq, float* __restrict__ Ck, float* __restrict__ Cv)
{
    extern __shared__ char dyns[];
    uint32_t sb = smem_u32(dyns);
    int bx = blockIdx.x, mBase = blockIdx.y * 128;
    if (bx < 16)      gemm_body(Ah, Al, WqH, WqL, Cq, HID,   HID, mBase, bx*128,      sb);
    else if (bx < 20) gemm_body(Ah, Al, WkH, WkL, Ck, KVDIM, HID, mBase, (bx-16)*128, sb);
    else              gemm_body(Ah, Al, WvH, WvL, Cv, KVDIM, HID, mBase, (bx-20)*128, sb);
}

__global__ __launch_bounds__(256)
void wo_gemm(const bf16* __restrict__ Ah, const bf16* __restrict__ Al,
             const bf16* __restrict__ Bh, const bf16* __restrict__ Bl,
             float* __restrict__ C)
{
    extern __shared__ char dyns[];
    uint32_t sb = smem_u32(dyns);
    gemm_body(Ah, Al, Bh, Bl, C, HID, HID, blockIdx.y*128, blockIdx.x*128, sb);
}

// ---------------- RoPE + split: Q (per-row variant, scaled), bK/nK, V ------
__device__ __forceinline__ void split_w(bf16* hp, bf16* lp, float x) {
    bf16 h = __float2bfloat16(x);
    *hp = h;
    *lp = __float2bfloat16(x - __bfloat162float(h));
}

__global__ void rope_split_kernel(const float* __restrict__ Q, const float* __restrict__ K,
                                  const float* __restrict__ V,
                                  bf16* __restrict__ qh, bf16* __restrict__ ql,
                                  bf16* __restrict__ kbh, bf16* __restrict__ kbl,
                                  bf16* __restrict__ knh, bf16* __restrict__ knl,
                                  bf16* __restrict__ vh, bf16* __restrict__ vl)
{
    const int s = blockIdx.x;
    const int tid = threadIdx.x; // 256
    const bool narrowRow = (s >= CTX);
    const float QS = 1.4426950408889634f * 0.125f;   // log2(e)/sqrt(64)

    __shared__ float cb[32], sb[32], cn[32], sn[32];
    if (tid < 32) {
        double inv = pow(10000.0, -(double)tid / 32.0);
        double ab = (double)s * inv;
        double an = ((double)s * 0.25) * inv;
        cb[tid] = (float)cos(ab); sb[tid] = (float)sin(ab);
        cn[tid] = (float)cos(an); sn[tid] = (float)sin(an);
    }
    __syncthreads();

    for (int p = tid; p < NH * 32; p += 256) {
        int h = p >> 5, d = p & 31;
        size_t base = (size_t)s * HID + h * HD;
        float x1 = Q[base + d];
        float x2 = Q[base + d + 32];
        float c  = narrowRow ? cn[d] : cb[d];
        float si = narrowRow ? sn[d] : sb[d];
        split_w(qh + base + d,      ql + base + d,      (x1 * c - x2 * si) * QS);
        split_w(qh + base + d + 32, ql + base + d + 32, (x2 * c + x1 * si) * QS);
    }
    for (int p = tid; p < NKV * 32; p += 256) {
        int h = p >> 5, d = p & 31;
        size_t base = (size_t)s * KVDIM + h * HD;
        float x1 = K[base + d];
        float x2 = K[base + d + 32];
        split_w(kbh + base + d,      kbl + base + d,      x1 * cb[d] - x2 * sb[d]);
        split_w(kbh + base + d + 32, kbl + base + d + 32, x2 * cb[d] + x1 * sb[d]);
        split_w(knh + base + d,      knl + base + d,      x1 * cn[d] - x2 * sn[d]);
        split_w(knh + base + d + 32, knl + base + d + 32, x2 * cn[d] + x1 * sn[d]);
    }
    for (int e = tid; e < KVDIM; e += 256) {
        size_t base = (size_t)s * KVDIM + e;
        split_w(vh + base, vl + base, V[base]);
    }
}

// ---------------- Tensor-core flash attention (R5-exact body) --------------
// CTA: 64 q-rows x 1 head. 4 warps x 16 rows. Bc=64 key tiles, double-buffered.
// Boost K only; rows >= CTX are recomputed by fixup_kernel afterwards.
// fp32 output write (split to bf16 happens in a separate pass).

__device__ __forceinline__ void fa_load_stage(
    uint32_t sb, int kt, int kvh, int tid,
    const bf16* __restrict__ Kbh, const bf16* __restrict__ Kbl,
    const bf16* __restrict__ Vh, const bf16* __restrict__ Vl)
{
#pragma unroll
    for (int i = 0; i < 4; i++) {
        int u = i * 128 + tid;      // 0..511
        int r = u >> 3, c = u & 7;
        uint32_t so = (uint32_t)(r * 128 + ((c ^ (r & 7)) << 4));
        size_t go = (size_t)(kt * 64 + r) * KVDIM + kvh * 64 + c * 8;
        cp16(sb +         so, Kbh + go);
        cp16(sb + 8192  + so, Kbl + go);
        cp16(sb + 16384 + so, Vh + go);
        cp16(sb + 24576 + so, Vl + go);
    }
}

__device__ __forceinline__ void fa_compute_S(
    float s[8][4], uint32_t sKh, uint32_t sKl,
    const uint32_t qfh[4][4], const uint32_t qfl[4][4], int lane)
{
#pragma unroll
    for (int kk = 0; kk < 4; kk++) {
        uint32_t kh[8][2], kl[8][2];
        int rB0 = (lane & 7) + ((lane >> 4) << 3);
        int ccB = kk * 2 + ((lane >> 3) & 1);
#pragma unroll
        for (int nb = 0; nb < 4; nb++) {
            int r = nb * 16 + rB0;
            uint32_t so = (uint32_t)(r * 128 + ((ccB ^ (r & 7)) << 4));
            ldsm_x4(sKh + so, kh[nb*2][0], kh[nb*2][1], kh[nb*2+1][0], kh[nb*2+1][1]);
            ldsm_x4(sKl + so, kl[nb*2][0], kl[nb*2][1], kl[nb*2+1][0], kl[nb*2+1][1]);
        }
#pragma unroll
        for (int nf = 0; nf < 8; nf++) {
            mma16816(s[nf], qfh[kk], kh[nf]);
            mma16816(s[nf], qfl[kk], kh[nf]);
            mma16816(s[nf], qfh[kk], kl[nf]);
        }
    }
}

#define FA_STAGE 32768
#define FA_SMEM  (16384 + 2*FA_STAGE)   // 81920

__global__ __launch_bounds__(128, 2)
void flash_mma(const bf16* __restrict__ Qh, const bf16* __restrict__ Ql,
               const bf16* __restrict__ Kbh, const bf16* __restrict__ Kbl,
               const bf16* __restrict__ Vh,  const bf16* __restrict__ Vl,
               float* __restrict__ attnOut)
{
    extern __shared__ char dyn[];
    const uint32_t sQ = smem_u32(dyn);           // Qh 8K | Ql 8K | stage0 | stage1

    const int tid = threadIdx.x, lane = tid & 31, w = tid >> 5;
    const int qt = (S/64 - 1) - (int)blockIdx.x;   // heavy first
    const int h = blockIdx.y, kvh = h >> 2;

    // ---- Q tile load (hi+lo) ----
    {
        const bf16* gQh = Qh + (size_t)(qt * 64) * HID + h * 64;
        const bf16* gQl = Ql + (size_t)(qt * 64) * HID + h * 64;
#pragma unroll
        for (int i = 0; i < 4; i++) {
            int u = i * 128 + tid;
            int r = u >> 3, c = u & 7;
            uint32_t so = (uint32_t)(r * 128 + ((c ^ (r & 7)) << 4));
            cp16(sQ +        so, gQh + (size_t)r * HID + c * 8);
            cp16(sQ + 8192 + so, gQl + (size_t)r * HID + c * 8);
        }
    }
    fa_load_stage(sQ + 16384, 0, kvh, tid, Kbh, Kbl, Vh, Vl);
    CP_COMMIT();
    if (qt >= 1)
        fa_load_stage(sQ + 16384 + FA_STAGE, 1, kvh, tid, Kbh, Kbl, Vh, Vl);
    CP_COMMIT();

    CP_WAIT1();
    __syncthreads();

    // ---- Q fragments (kept in registers for all tiles) ----
    uint32_t qfh[4][4], qfl[4][4];
    {
        int rA = w * 16 + (lane & 15);
#pragma unroll
        for (int kk = 0; kk < 4; kk++) {
            int cc = kk * 2 + (lane >> 4);
            uint32_t so = (uint32_t)(rA * 128 + ((cc ^ (rA & 7)) << 4));
            ldsm_x4(sQ + so,        qfh[kk][0], qfh[kk][1], qfh[kk][2], qfh[kk][3]);
            ldsm_x4(sQ + 8192 + so, qfl[kk][0], qfl[kk][1], qfl[kk][2], qfl[kk][3]);
        }
    }

    float o[8][4];
#pragma unroll
    for (int nf = 0; nf < 8; nf++)
#pragma unroll
        for (int j = 0; j < 4; j++) o[nf][j] = 0.0f;
    float m0 = -1e30f, m1 = -1e30f, l0 = 0.0f, l1 = 0.0f;

    const int rg0 = qt * 64 + w * 16 + (lane >> 2);
    const int rg1 = rg0 + 8;

    for (int kt = 0; kt <= qt; kt++) {
        if (kt) { CP_WAIT1(); __syncthreads(); }
        const uint32_t sb = sQ + 16384 + (kt & 1) * FA_STAGE;

        // ---- S = Q K^T ----
        float s[8][4];
#pragma unroll
        for (int nf = 0; nf < 8; nf++)
#pragma unroll
            for (int j = 0; j < 4; j++) s[nf][j] = 0.0f;
        fa_compute_S(s, sb, sb + 8192, qfh, qfl, lane);

        // ---- causal mask (diagonal tile only) ----
        if (kt == qt) {
#pragma unroll
            for (int nf = 0; nf < 8; nf++) {
                int c0 = kt * 64 + nf * 8 + (lane & 3) * 2;
                if (c0     > rg0) s[nf][0] = -1e30f;
                if (c0 + 1 > rg0) s[nf][1] = -1e30f;
                if (c0     > rg1) s[nf][2] = -1e30f;
                if (c0 + 1 > rg1) s[nf][3] = -1e30f;
            }
        }

        // ---- online softmax (base-2; scale folded into Q) ----
        float mr0 = -1e30f, mr1 = -1e30f;
#pragma unroll
        for (int nf = 0; nf < 8; nf++) {
            mr0 = fmaxf(mr0, fmaxf(s[nf][0], s[nf][1]));
            mr1 = fmaxf(mr1, fmaxf(s[nf][2], s[nf][3]));
        }
        mr0 = fmaxf(mr0, __shfl_xor_sync(0xffffffffu, mr0, 1));
        mr0 = fmaxf(mr0, __shfl_xor_sync(0xffffffffu, mr0, 2));
        mr1 = fmaxf(mr1, __shfl_xor_sync(0xffffffffu, mr1, 1));
        mr1 = fmaxf(mr1, __shfl_xor_sync(0xffffffffu, mr1, 2));

        float mn0 = fmaxf(m0, mr0), mn1 = fmaxf(m1, mr1);
        float sc0 = exp2f(m0 - mn0), sc1 = exp2f(m1 - mn1);
        m0 = mn0; m1 = mn1;
        l0 *= sc0; l1 *= sc1;
#pragma unroll
        for (int nf = 0; nf < 8; nf++) {
            o[nf][0] *= sc0; o[nf][1] *= sc0;
            o[nf][2] *= sc1; o[nf][3] *= sc1;
        }

        uint32_t pH[4][4], pL[4][4];
        float sum0 = 0.0f, sum1 = 0.0f;
#pragma unroll
        for (int nf = 0; nf < 8; nf++) {
            float p0 = exp2f(s[nf][0] - m0), p1 = exp2f(s[nf][1] - m0);
            float p2 = exp2f(s[nf][2] - m1), p3 = exp2f(s[nf][3] - m1);
            sum0 += p0 + p1; sum1 += p2 + p3;
            float r0 = __bfloat162float(__float2bfloat16(p0));
            float r1 = __bfloat162float(__float2bfloat16(p1));
            float r2 = __bfloat162float(__float2bfloat16(p2));
            float r3 = __bfloat162float(__float2bfloat16(p3));
            int kk = nf >> 1;
            int off = (nf & 1) * 2;
            pH[kk][off + 0] = pack_bf16x2(p0, p1);
            pH[kk][off + 1] = pack_bf16x2(p2, p3);
            pL[kk][off + 0] = pack_bf16x2(p0 - r0, p1 - r1);
            pL[kk][off + 1] = pack_bf16x2(p2 - r2, p3 - r3);
        }
        sum0 += __shfl_xor_sync(0xffffffffu, sum0, 1);
        sum0 += __shfl_xor_sync(0xffffffffu, sum0, 2);
        sum1 += __shfl_xor_sync(0xffffffffu, sum1, 1);
        sum1 += __shfl_xor_sync(0xffffffffu, sum1, 2);
        l0 += sum0; l1 += sum1;

        // ---- O += P V ----
        const uint32_t sVh = sb + 16384, sVl = sb + 24576;
#pragma unroll
        for (int kk = 0; kk < 4; kk++) {
            uint32_t vh[8][2], vl[8][2];
            int key0 = kk * 16 + (lane & 7) + ((lane >> 3) & 1) * 8;
#pragma unroll
            for (int nb = 0; nb < 4; nb++) {
                int chunk = nb * 2 + (lane >> 4);
                uint32_t so = (uint32_t)(key0 * 128 + ((chunk ^ (key0 & 7)) << 4));
                ldsm_x4t(sVh + so, vh[nb*2][0], vh[nb*2][1], vh[nb*2+1][0], vh[nb*2+1][1]);
                ldsm_x4t(sVl + so, vl[nb*2][0], vl[nb*2][1], vl[nb*2+1][0], vl[nb*2+1][1]);
            }
#pragma unroll
            for (int nf = 0; nf < 8; nf++) {
                mma16816(o[nf], pH[kk], vh[nf]);
                mma16816(o[nf], pL[kk], vh[nf]);
                mma16816(o[nf], pH[kk], vl[nf]);
            }
        }

        __syncthreads();
        if (kt + 2 <= qt)
            fa_load_stage(sQ + 16384 + (kt & 1) * FA_STAGE, kt + 2, kvh, tid,
                          Kbh, Kbl, Vh, Vl);
        CP_COMMIT();
    }

    // ---- epilogue: fp32 write (R5-exact) ----
    float inv0 = 1.0f / l0, inv1 = 1.0f / l1;
#pragma unroll
    for (int nf = 0; nf < 8; nf++) {
        int col = h * 64 + nf * 8 + (lane & 3) * 2;
        *(float2*)&attnOut[(size_t)rg0 * HID + col] = make_float2(o[nf][0]*inv0, o[nf][1]*inv0);
        *(float2*)&attnOut[(size_t)rg1 * HID + col] = make_float2(o[nf][2]*inv1, o[nf][3]*inv1);
    }
}

// ---------------- fixup: recompute rows >= CTX with narrow K (coalesced) ----
// One CTA per (row, head): 320 CTAs x 256 threads. fp32 output into g_attn.
__global__ __launch_bounds__(256)
void fixup_kernel(const bf16* __restrict__ Qh, const bf16* __restrict__ Ql,
                  const bf16* __restrict__ nKh, const bf16* __restrict__ nKl,
                  const bf16* __restrict__ Vh,  const bf16* __restrict__ Vl,
                  float* __restrict__ attnOut)
{
    const int pair = blockIdx.x;            // 0..319
    const int ri = pair >> 5;                // 0..9
    const int h  = pair & 31;
    const int row = CTX + ri;
    const int kvh = h >> 2;
    const int tid = threadIdx.x, lane = tid & 31, w = tid >> 5;
    const int nkeys = row + 1;

    __shared__ float qsm[64];
    __shared__ float sc[S];
    __shared__ float red[8];
    __shared__ float oacc[4][64];

    if (tid < 64) {
        size_t off = (size_t)row * HID + h * 64 + tid;
        qsm[tid] = __bfloat162float(Qh[off]) + __bfloat162float(Ql[off]);  // scaled (base-2)
    }
    __syncthreads();

    // ---- phase 1: scores (warp per key, lanes over dims) ----
    const float q0 = qsm[lane * 2], q1 = qsm[lane * 2 + 1];
    for (int j = w; j < nkeys; j += 8) {
        size_t off = (size_t)j * KVDIM + kvh * 64;
        __nv_bfloat162 a = ((const __nv_bfloat162*)(nKh + off))[lane];
        __nv_bfloat162 b = ((const __nv_bfloat162*)(nKl + off))[lane];
        float kx = __bfloat162float(a.x) + __bfloat162float(b.x);
        float ky = __bfloat162float(a.y) + __bfloat162float(b.y);
        float s = q0 * kx + q1 * ky;
#pragma unroll
        for (int d = 16; d; d >>= 1) s += __shfl_xor_sync(0xffffffffu, s, d);
        if (lane == 0) sc[j] = s;
    }
    __syncthreads();

    // ---- max reduce ----
    float mym = -1e30f;
    for (int j = tid; j < nkeys; j += 256) mym = fmaxf(mym, sc[j]);
#pragma unroll
    for (int d = 16; d; d >>= 1) mym = fmaxf(mym, __shfl_xor_sync(0xffffffffu, mym, d));
    if (lane == 0) red[w] = mym;
    __syncthreads();
    float M = red[0];
#pragma unroll
    for (int i = 1; i < 8; i++) M = fmaxf(M, red[i]);
    __syncthreads();

    // ---- p = exp2(s - M), sum ----
    float ls = 0.0f;
    for (int j = tid; j < nkeys; j += 256) {
        float p = exp2f(sc[j] - M);
        sc[j] = p;
        ls += p;
    }
#pragma unroll
    for (int d = 16; d; d >>= 1) ls += __shfl_xor_sync(0xffffffffu, ls, d);
    if (lane == 0) red[w] = ls;
    __syncthreads();
    float L = red[0];
#pragma unroll
    for (int i = 1; i < 8; i++) L += red[i];

    // ---- phase 2: O = sum p_j V_j (thread = dim x key-chunk, coalesced) ----
    const int d = tid & 63, ch = tid >> 6;   // 4 chunks
    float acc = 0.0f;
    for (int j = ch; j < nkeys; j += 4) {
        size_t off = (size_t)j * KVDIM + kvh * 64 + d;
        acc += sc[j] * (__bfloat162float(Vh[off]) + __bfloat162float(Vl[off]));
    }
    oacc[ch][d] = acc;
    __syncthreads();

    if (tid < 64) {
        float o = (oacc[0][tid] + oacc[1][tid] + oacc[2][tid] + oacc[3][tid]) / L;
        attnOut[(size_t)row * HID + h * 64 + tid] = o;
    }
}

// ---------------- launch ----------------
extern "C" void kernel_launch(void* const* d_in, const int* in_sizes, int n_in,
                              void* d_out, int out_size)
{
    const float* hidden = (const float*)d_in[0];
    const float* Wq = (const float*)d_in[3];
    const float* Wk = (const float*)d_in[4];
    const float* Wv = (const float*)d_in[5];
    const float* Wo = (const float*)d_in[6];
    float* out = (float*)d_out;

    float *qB, *kB, *vB, *atB;
    cudaGetSymbolAddress((void**)&qB,  g_Q);
    cudaGetSymbolAddress((void**)&kB,  g_K);
    cudaGetSymbolAddress((void**)&vB,  g_V);
    cudaGetSymbolAddress((void**)&atB, g_attn);

    bf16 *hH,*hL,*WqH,*WqL,*WkH,*WkL,*WvH,*WvL,*WoH,*WoL,*aH,*aL;
    cudaGetSymbolAddress((void**)&hH,  g_hH);  cudaGetSymbolAddress((void**)&hL,  g_hL);
    cudaGetSymbolAddress((void**)&WqH, g_WqH); cudaGetSymbolAddress((void**)&WqL, g_WqL);
    cudaGetSymbolAddress((void**)&WkH, g_WkH); cudaGetSymbolAddress((void**)&WkL, g_WkL);
    cudaGetSymbolAddress((void**)&WvH, g_WvH); cudaGetSymbolAddress((void**)&WvL, g_WvL);
    cudaGetSymbolAddress((void**)&WoH, g_WoH); cudaGetSymbolAddress((void**)&WoL, g_WoL);
    cudaGetSymbolAddress((void**)&aH,  g_aH);  cudaGetSymbolAddress((void**)&aL,  g_aL);

    bf16 *Qh,*Ql,*bKh,*bKl,*nKh,*nKl,*Vh,*Vl;
    cudaGetSymbolAddress((void**)&Qh,  g_Qh);  cudaGetSymbolAddress((void**)&Ql,  g_Ql);
    cudaGetSymbolAddress((void**)&bKh, g_bKh); cudaGetSymbolAddress((void**)&bKl, g_bKl);
    cudaGetSymbolAddress((void**)&nKh, g_nKh); cudaGetSymbolAddress((void**)&nKl, g_nKl);
    cudaGetSymbolAddress((void**)&Vh,  g_Vh);  cudaGetSymbolAddress((void**)&Vl,  g_Vl);

    cudaFuncSetAttribute(qkv_gemm, cudaFuncAttributeMaxDynamicSharedMemorySize, SM_TOTAL);
    cudaFuncSetAttribute(wo_gemm,  cudaFuncAttributeMaxDynamicSharedMemorySize, SM_TOTAL);
    cudaFuncSetAttribute(flash_mma, cudaFuncAttributeMaxDynamicSharedMemorySize, FA_SMEM);

    // one merged split launch for all 5 fp32 inputs
    const int TOT4 = 1048576*3 + 262144*2;   // 3.67M float4
    split_all_kernel<<<(TOT4 + 255)/256, 256>>>(hidden, Wq, Wk, Wv, Wo,
                                                hH, hL, WqH, WqL, WkH, WkL,
                                                WvH, WvL, WoH, WoL);

    qkv_gemm<<<dim3(24, 16), 256, SM_TOTAL>>>(hH, hL, WqH, WqL, WkH, WkL, WvH, WvL,
                                              qB, kB, vB);

    rope_split_kernel<<<S, 256>>>(qB, kB, vB, Qh, Ql, bKh, bKl, nKh, nKl, Vh, Vl);

    // all 32 q-tiles, heavy first (boost K; narrow rows fixed up after)
    flash_mma<<<dim3(S/64, NH), 128, FA_SMEM>>>(Qh, Ql, bKh, bKl, Vh, Vl, atB);
    fixup_kernel<<<320, 256>>>(Qh, Ql, nKh, nKl, Vh, Vl, atB);

    split4_kernel<<<(S*HID/4 + 255)/256, 256>>>(atB, aH, aL, S*HID/4);
    wo_gemm<<<dim3(16, 16), 256, SM_TOTAL>>>(aH, aL, WoH, WoL, out);
}